// round 1
// baseline (speedup 1.0000x reference)
#include <cuda_runtime.h>
#include <math.h>

#define BATCH 8
#define NN 2048
#define FF 256
#define BN (BATCH * NN)        // 16384
#define ALPHA 0.2f

// ---------------- scratch (static device allocations; no cudaMalloc) --------
__device__ float d_Wh[(size_t)BN * FF];          // 16 MB
__device__ float d_wl[(size_t)BN * FF];          // 16 MB
__device__ float d_s1[BN];
__device__ float d_s2[BN];
__device__ float d_v[2 * FF];
__device__ float d_att[(size_t)BATCH * NN * NN]; // 134 MB

// ---------------- kernel 1: v1 = W1 @ a[:F], v2 = W1 @ a[F:] ----------------
__global__ void v_kernel(const float* __restrict__ W1, const float* __restrict__ a,
                         float* __restrict__ v) {
    int k = threadIdx.x;   // 0..255
    float acc1 = 0.f, acc2 = 0.f;
    const float* wrow = W1 + (size_t)k * FF;
#pragma unroll 8
    for (int c = 0; c < FF; c++) {
        float w = wrow[c];
        acc1 += w * a[c];
        acc2 += w * a[FF + c];
    }
    v[k] = acc1;
    v[FF + k] = acc2;
}

// ---------------- kernel 2: Wh = h @ W1 ; wl = lrgt1 @ W2 -------------------
// 64x64 tile, 256 threads, 4x4 per thread, K-tile 16.
__global__ void feat_gemm(const float* __restrict__ h, const float* __restrict__ lr,
                          const float* __restrict__ W1, const float* __restrict__ W2,
                          float* __restrict__ Wh, float* __restrict__ wl) {
    const float* A;
    const float* W;
    float* C;
    if (blockIdx.z == 0) { A = h;  W = W1; C = Wh; }
    else                 { A = lr; W = W2; C = wl; }

    int m0 = blockIdx.x * 64;
    int n0 = blockIdx.y * 64;
    __shared__ float As[16][66];   // padded: conflict-free transposed stores
    __shared__ float Ws[16][64];

    int tid = threadIdx.x;
    int tx = tid & 15, ty = tid >> 4;
    float acc[4][4] = {};

    for (int k0 = 0; k0 < FF; k0 += 16) {
        {
            int row = tid >> 2;
            int kq = (tid & 3) * 4;
            float4 va = *(const float4*)(A + (size_t)(m0 + row) * FF + k0 + kq);
            As[kq + 0][row] = va.x; As[kq + 1][row] = va.y;
            As[kq + 2][row] = va.z; As[kq + 3][row] = va.w;

            int wr = tid >> 4;
            int c4 = (tid & 15) * 4;
            *(float4*)&Ws[wr][c4] = *(const float4*)(W + (size_t)(k0 + wr) * FF + n0 + c4);
        }
        __syncthreads();
#pragma unroll
        for (int kk = 0; kk < 16; kk++) {
            float av[4], bv[4];
#pragma unroll
            for (int i = 0; i < 4; i++) av[i] = As[kk][ty + 16 * i];
#pragma unroll
            for (int j = 0; j < 4; j++) bv[j] = Ws[kk][tx + 16 * j];
#pragma unroll
            for (int i = 0; i < 4; i++)
#pragma unroll
                for (int j = 0; j < 4; j++) acc[i][j] += av[i] * bv[j];
        }
        __syncthreads();
    }
#pragma unroll
    for (int i = 0; i < 4; i++)
#pragma unroll
        for (int j = 0; j < 4; j++)
            C[(size_t)(m0 + ty + 16 * i) * FF + n0 + tx + 16 * j] = acc[i][j];
}

// ---------------- kernel 3: s1 = h.v1, s2 = h.v2 (exact fp32) ---------------
__global__ void scores_kernel(const float* __restrict__ h, const float* __restrict__ v,
                              float* __restrict__ s1, float* __restrict__ s2) {
    int r = blockIdx.x;         // 0..BN-1
    int tid = threadIdx.x;      // 256
    float hv = h[(size_t)r * FF + tid];
    float p1 = hv * v[tid];
    float p2 = hv * v[FF + tid];
    __shared__ float r1[256];
    __shared__ float r2[256];
    r1[tid] = p1; r2[tid] = p2;
    __syncthreads();
    for (int s = 128; s > 0; s >>= 1) {
        if (tid < s) { r1[tid] += r1[tid + s]; r2[tid] += r2[tid + s]; }
        __syncthreads();
    }
    if (tid == 0) { s1[r] = r1[0]; s2[r] = r2[0]; }
}

// ---------------- kernel 4: masked leaky-relu softmax row -------------------
__global__ void softmax_kernel(const int* __restrict__ adj, const float* __restrict__ s1,
                               const float* __restrict__ s2, float* __restrict__ att) {
    int bi = blockIdx.x;            // 0..BN-1  (b = bi>>11, i = bi&2047)
    int b = bi >> 11;
    const int* arow = adj + (size_t)bi * NN;
    const float* s2b = s2 + (size_t)b * NN;
    float si = s1[bi];

    __shared__ float x[NN];         // 8 KB
    __shared__ float red[256];
    int tid = threadIdx.x;

    float lmax = -3.4e38f;
#pragma unroll
    for (int j = tid; j < NN; j += 256) {
        float val = si + s2b[j];
        val = val > 0.f ? val : ALPHA * val;        // leaky relu
        val = arow[j] > 0 ? val : -9.0e15f;         // mask
        x[j] = val;
        lmax = fmaxf(lmax, val);
    }
    red[tid] = lmax;
    __syncthreads();
    for (int s = 128; s > 0; s >>= 1) {
        if (tid < s) red[tid] = fmaxf(red[tid], red[tid + s]);
        __syncthreads();
    }
    float m = red[0];
    __syncthreads();

    float lsum = 0.f;
#pragma unroll
    for (int j = tid; j < NN; j += 256) {
        float e = __expf(x[j] - m);    // exp(-9e15 - m) underflows to 0 as intended
        x[j] = e;
        lsum += e;
    }
    red[tid] = lsum;
    __syncthreads();
    for (int s = 128; s > 0; s >>= 1) {
        if (tid < s) red[tid] += red[tid + s];
        __syncthreads();
    }
    float inv = 1.f / red[0];
    float* orow = att + (size_t)bi * NN;
#pragma unroll
    for (int j = tid; j < NN; j += 256) orow[j] = x[j] * inv;
}

// ---------------- kernel 5: [out1,out2] = att @ [Wh, wl], elu ---------------
// Block tile 128x64, 256 threads, per-thread 8x4 for each of two outputs.
__device__ __forceinline__ float elu_f(float v) {
    return v > 0.f ? v : (expf(v) - 1.f);
}

__global__ void attn_gemm(const float* __restrict__ att, const float* __restrict__ Wh,
                          const float* __restrict__ wl, float* __restrict__ out) {
    int b = blockIdx.z;
    int m0 = blockIdx.x * 128;
    int n0 = blockIdx.y * 64;
    const float* A  = att + (size_t)b * NN * NN;
    const float* B1 = Wh + (size_t)b * NN * FF;
    const float* B2 = wl + (size_t)b * NN * FF;

    __shared__ float As[16][130];      // padded stride 130: conflict-free stores
    __shared__ float Bs[2][16][64];

    int tid = threadIdx.x;
    int tx = tid & 15, ty = tid >> 4;
    float acc1[8][4] = {};
    float acc2[8][4] = {};

    for (int k0 = 0; k0 < NN; k0 += 16) {
        // A tile: 128 rows x 16 cols  (512 float4 slots, 2 per thread)
#pragma unroll
        for (int s = tid; s < 512; s += 256) {
            int row = s >> 2;
            int kq = (s & 3) * 4;
            float4 va = *(const float4*)(A + (size_t)(m0 + row) * NN + k0 + kq);
            As[kq + 0][row] = va.x; As[kq + 1][row] = va.y;
            As[kq + 2][row] = va.z; As[kq + 3][row] = va.w;
        }
        // B tiles: 16 x 64 each
        {
            int row = tid >> 4;
            int c4 = (tid & 15) * 4;
            *(float4*)&Bs[0][row][c4] = *(const float4*)(B1 + (size_t)(k0 + row) * FF + n0 + c4);
            *(float4*)&Bs[1][row][c4] = *(const float4*)(B2 + (size_t)(k0 + row) * FF + n0 + c4);
        }
        __syncthreads();
#pragma unroll
        for (int kk = 0; kk < 16; kk++) {
            float av[8], b1[4], b2[4];
#pragma unroll
            for (int i = 0; i < 8; i++) av[i] = As[kk][ty + 16 * i];
#pragma unroll
            for (int j = 0; j < 4; j++) { b1[j] = Bs[0][kk][tx + 16 * j]; b2[j] = Bs[1][kk][tx + 16 * j]; }
#pragma unroll
            for (int i = 0; i < 8; i++)
#pragma unroll
                for (int j = 0; j < 4; j++) {
                    acc1[i][j] += av[i] * b1[j];
                    acc2[i][j] += av[i] * b2[j];
                }
        }
        __syncthreads();
    }

    float* o1 = out + (size_t)b * NN * FF;
    float* o2 = out + (size_t)BATCH * NN * FF + (size_t)b * NN * FF;
#pragma unroll
    for (int i = 0; i < 8; i++) {
        int m = m0 + ty + 16 * i;
#pragma unroll
        for (int j = 0; j < 4; j++) {
            int n = n0 + tx + 16 * j;
            o1[(size_t)m * FF + n] = elu_f(acc1[i][j]);
            o2[(size_t)m * FF + n] = elu_f(acc2[i][j]);
        }
    }
}

// ---------------------------------------------------------------------------
extern "C" void kernel_launch(void* const* d_in, const int* in_sizes, int n_in,
                              void* d_out, int out_size) {
    const float* h     = (const float*)d_in[0];
    const int*   adj   = (const int*)  d_in[1];
    const float* lrgt1 = (const float*)d_in[2];
    const float* W1    = (const float*)d_in[3];
    const float* W2    = (const float*)d_in[4];
    const float* a     = (const float*)d_in[5];
    float* out = (float*)d_out;

    float* Wh;  cudaGetSymbolAddress((void**)&Wh,  d_Wh);
    float* wl;  cudaGetSymbolAddress((void**)&wl,  d_wl);
    float* s1;  cudaGetSymbolAddress((void**)&s1,  d_s1);
    float* s2;  cudaGetSymbolAddress((void**)&s2,  d_s2);
    float* v;   cudaGetSymbolAddress((void**)&v,   d_v);
    float* att; cudaGetSymbolAddress((void**)&att, d_att);

    // 1. a-projection vectors (exact fp32 path for logits)
    v_kernel<<<1, 256>>>(W1, a, v);

    // 2. feature GEMMs: Wh = h@W1, wl = lrgt1@W2
    {
        dim3 grid(BN / 64, FF / 64, 2);
        feat_gemm<<<grid, 256>>>(h, lrgt1, W1, W2, Wh, wl);
    }

    // 3. logit scores s1 = h.v1, s2 = h.v2
    scores_kernel<<<BN, 256>>>(h, v, s1, s2);

    // 4. masked softmax rows -> att
    softmax_kernel<<<BN, 256>>>(adj, s1, s2, att);

    // 5. dual GEMM att@Wh, att@wl + ELU epilogue
    {
        dim3 grid(NN / 128, FF / 64, BATCH);
        attn_gemm<<<grid, 256>>>(att, Wh, wl, out);
    }
}

// round 3
// speedup vs baseline: 1.9910x; 1.9910x over previous
#include <cuda_runtime.h>
#include <cuda_bf16.h>
#include <cstdint>
#include <math.h>

#define BATCH 8
#define NN 2048
#define FF 256
#define NFEAT 512              // Wh (256) stacked with wl (256)
#define BN (BATCH * NN)        // 16384
#define ALPHA 0.2f

// ---------------- scratch (static device allocations; no cudaMalloc) --------
__device__ float d_BT[(size_t)BATCH * NFEAT * NN];   // 32 MB, [b][feat][node]
__device__ float d_s1[BN];
__device__ float d_s2[BN];
__device__ float d_v[2 * FF];
__device__ float d_att[(size_t)BATCH * NN * NN];     // 134 MB

// ---------------- kernel 1: v1 = W1 @ a[:F], v2 = W1 @ a[F:] ----------------
__global__ void v_kernel(const float* __restrict__ W1, const float* __restrict__ a,
                         float* __restrict__ v) {
    int k = threadIdx.x;
    float acc1 = 0.f, acc2 = 0.f;
    const float* wrow = W1 + (size_t)k * FF;
#pragma unroll 8
    for (int c = 0; c < FF; c++) {
        float w = wrow[c];
        acc1 += w * a[c];
        acc2 += w * a[FF + c];
    }
    v[k] = acc1;
    v[FF + k] = acc2;
}

// ---- kernel 2: BT[b][z*256+n][node] = (h@W1 / lr@W2)[b,node,n] (transposed) -
__global__ void feat_gemm(const float* __restrict__ h, const float* __restrict__ lr,
                          const float* __restrict__ W1, const float* __restrict__ W2,
                          float* __restrict__ BT) {
    const float* A;
    const float* W;
    int z = blockIdx.z;
    if (z == 0) { A = h;  W = W1; }
    else        { A = lr; W = W2; }

    int m0 = blockIdx.x * 64;
    int n0 = blockIdx.y * 64;
    __shared__ float As[16][66];
    __shared__ float Ws[16][64];
    __shared__ float Ct[64][65];

    int tid = threadIdx.x;
    int tx = tid & 15, ty = tid >> 4;
    float acc[4][4] = {};

    for (int k0 = 0; k0 < FF; k0 += 16) {
        {
            int row = tid >> 2;
            int kq = (tid & 3) * 4;
            float4 va = *(const float4*)(A + (size_t)(m0 + row) * FF + k0 + kq);
            As[kq + 0][row] = va.x; As[kq + 1][row] = va.y;
            As[kq + 2][row] = va.z; As[kq + 3][row] = va.w;
            int wr = tid >> 4;
            int c4 = (tid & 15) * 4;
            *(float4*)&Ws[wr][c4] = *(const float4*)(W + (size_t)(k0 + wr) * FF + n0 + c4);
        }
        __syncthreads();
#pragma unroll
        for (int kk = 0; kk < 16; kk++) {
            float av[4], bv[4];
#pragma unroll
            for (int i = 0; i < 4; i++) av[i] = As[kk][ty + 16 * i];
#pragma unroll
            for (int j = 0; j < 4; j++) bv[j] = Ws[kk][tx + 16 * j];
#pragma unroll
            for (int i = 0; i < 4; i++)
#pragma unroll
                for (int j = 0; j < 4; j++) acc[i][j] += av[i] * bv[j];
        }
        __syncthreads();
    }
#pragma unroll
    for (int i = 0; i < 4; i++)
#pragma unroll
        for (int j = 0; j < 4; j++)
            Ct[tx + 16 * j][ty + 16 * i] = acc[i][j];
    __syncthreads();
    int b = m0 >> 11;
    int node0 = m0 & (NN - 1);
    int fl = tid >> 2;
    int cs = (tid & 3) * 16;
    float* dst = BT + (size_t)b * NFEAT * NN + (size_t)(z * 256 + n0 + fl) * NN + node0 + cs;
#pragma unroll
    for (int c = 0; c < 16; c += 4) {
        float4 v;
        v.x = Ct[fl][cs + c]; v.y = Ct[fl][cs + c + 1];
        v.z = Ct[fl][cs + c + 2]; v.w = Ct[fl][cs + c + 3];
        *(float4*)(dst + c) = v;
    }
}

// ---------------- kernel 3: s1 = h.v1, s2 = h.v2 (exact fp32) ---------------
__global__ void scores_kernel(const float* __restrict__ h, const float* __restrict__ v,
                              float* __restrict__ s1, float* __restrict__ s2) {
    int r = blockIdx.x;
    int tid = threadIdx.x;
    float hv = h[(size_t)r * FF + tid];
    float p1 = hv * v[tid];
    float p2 = hv * v[FF + tid];
    __shared__ float r1[256];
    __shared__ float r2[256];
    r1[tid] = p1; r2[tid] = p2;
    __syncthreads();
    for (int s = 128; s > 0; s >>= 1) {
        if (tid < s) { r1[tid] += r1[tid + s]; r2[tid] += r2[tid + s]; }
        __syncthreads();
    }
    if (tid == 0) { s1[r] = r1[0]; s2[r] = r2[0]; }
}

// ---------------- kernel 4: masked leaky-relu softmax row -------------------
__global__ void softmax_kernel(const int* __restrict__ adj, const float* __restrict__ s1,
                               const float* __restrict__ s2, float* __restrict__ att) {
    int bi = blockIdx.x;
    int b = bi >> 11;
    const int* arow = adj + (size_t)bi * NN;
    const float* s2b = s2 + (size_t)b * NN;
    float si = s1[bi];

    __shared__ float x[NN];
    __shared__ float red[256];
    int tid = threadIdx.x;

    float lmax = -3.4e38f;
#pragma unroll
    for (int j = tid; j < NN; j += 256) {
        float val = si + s2b[j];
        val = val > 0.f ? val : ALPHA * val;
        val = arow[j] > 0 ? val : -9.0e15f;
        x[j] = val;
        lmax = fmaxf(lmax, val);
    }
    red[tid] = lmax;
    __syncthreads();
    for (int s = 128; s > 0; s >>= 1) {
        if (tid < s) red[tid] = fmaxf(red[tid], red[tid + s]);
        __syncthreads();
    }
    float m = red[0];
    __syncthreads();

    float lsum = 0.f;
#pragma unroll
    for (int j = tid; j < NN; j += 256) {
        float e = __expf(x[j] - m);
        x[j] = e;
        lsum += e;
    }
    red[tid] = lsum;
    __syncthreads();
    for (int s = 128; s > 0; s >>= 1) {
        if (tid < s) red[tid] += red[tid + s];
        __syncthreads();
    }
    float inv = 1.f / red[0];
    float* orow = att + (size_t)bi * NN;
#pragma unroll
    for (int j = tid; j < NN; j += 256) orow[j] = x[j] * inv;
}

// ============== kernel 5: HMMA (mma.sync bf16x3) dual GEMM + ELU ============
// CTA tile 128(m) x 128(n), 8 warps (4m x 2n), warp tile 32x64.
// K-tile 32, double-buffered smem; rows padded to 80B (conflict-free ldmatrix).
#define KT 32
#define ROWB 80                        // 32 bf16 (64B) + 16B pad
#define ARR_BYTES (128 * ROWB)         // 10240
#define STAGE_BYTES (4 * ARR_BYTES)    // Ahi Alo Bhi Blo = 40960
#define SMEM_TOTAL (2 * STAGE_BYTES)   // 81920

__device__ __forceinline__ uint32_t smem_u32(const void* p) {
    uint32_t a;
    asm("{ .reg .u64 t; cvta.to.shared.u64 t, %1; cvt.u32.u64 %0, t; }"
        : "=r"(a) : "l"(p));
    return a;
}
__device__ __forceinline__ void ldsm_x4(uint32_t* r, uint32_t addr) {
    asm volatile("ldmatrix.sync.aligned.m8n8.x4.shared.b16 {%0,%1,%2,%3}, [%4];"
                 : "=r"(r[0]), "=r"(r[1]), "=r"(r[2]), "=r"(r[3]) : "r"(addr));
}
__device__ __forceinline__ void mma16816(float* d, const uint32_t* a, const uint32_t* b) {
    asm volatile(
        "mma.sync.aligned.m16n8k16.row.col.f32.bf16.bf16.f32 "
        "{%0,%1,%2,%3}, {%4,%5,%6,%7}, {%8,%9}, {%0,%1,%2,%3};"
        : "+f"(d[0]), "+f"(d[1]), "+f"(d[2]), "+f"(d[3])
        : "r"(a[0]), "r"(a[1]), "r"(a[2]), "r"(a[3]), "r"(b[0]), "r"(b[1]));
}
__device__ __forceinline__ void cvt4(float4 v, uint2& hi, uint2& lo) {
    union { __nv_bfloat16 h[4]; uint2 u; } H, L;
    H.h[0] = __float2bfloat16(v.x);
    H.h[1] = __float2bfloat16(v.y);
    H.h[2] = __float2bfloat16(v.z);
    H.h[3] = __float2bfloat16(v.w);
    L.h[0] = __float2bfloat16(v.x - __bfloat162float(H.h[0]));
    L.h[1] = __float2bfloat16(v.y - __bfloat162float(H.h[1]));
    L.h[2] = __float2bfloat16(v.z - __bfloat162float(H.h[2]));
    L.h[3] = __float2bfloat16(v.w - __bfloat162float(H.h[3]));
    hi = H.u; lo = L.u;
}
__device__ __forceinline__ float elu_f(float v) {
    return v > 0.f ? v : (expf(v) - 1.f);
}

__global__ void __launch_bounds__(256, 1)
attn_mma(const float* __restrict__ att, const float* __restrict__ BT,
         float* __restrict__ out) {
    extern __shared__ char smem[];
    const uint32_t sbase = smem_u32(smem);
    const int tid = threadIdx.x;
    const int wid = tid >> 5;
    const int lid = tid & 31;
    const int b = blockIdx.z;
    const int m0 = blockIdx.x * 128;
    const int n0g = blockIdx.y * 128;
    const float* A  = att + (size_t)b * NN * NN;
    const float* Bt = BT + (size_t)b * NFEAT * NN + (size_t)n0g * NN;

    const int wm = wid & 3;           // 0..3  -> rows wm*32
    const int wn = wid >> 2;          // 0..1  -> cols wn*64
    const int g  = lid >> 3;          // ldmatrix group
    const int r8 = lid & 7;

    // loader indices: 4 float4 per thread per matrix (128 rows x 8 quads)
    const int lrow = tid >> 3;        // base row (stride 32 over i)
    const int lkq  = (tid & 7) * 4;   // k quad

    float acc[2][8][4] = {};
    float4 regA[4], regB[4];

    // prologue: direct load of stage 0
    {
        char* dsthi = smem;              // Ahi stage 0
#pragma unroll
        for (int i = 0; i < 4; i++) {
            int row = lrow + i * 32;
            float4 va = *(const float4*)(A + (size_t)(m0 + row) * NN + lkq);
            float4 vb = *(const float4*)(Bt + (size_t)row * NN + lkq);
            uint2 hi, lo;
            uint32_t off = row * ROWB + lkq * 2;
            cvt4(va, hi, lo);
            *(uint2*)(dsthi + off) = hi;
            *(uint2*)(dsthi + ARR_BYTES + off) = lo;
            cvt4(vb, hi, lo);
            *(uint2*)(dsthi + 2 * ARR_BYTES + off) = hi;
            *(uint2*)(dsthi + 3 * ARR_BYTES + off) = lo;
        }
    }
    __syncthreads();

    const int NIT = NN / KT;   // 64
    for (int it = 0; it < NIT; it++) {
        int s = it & 1;
        // issue global loads for next tile (latency hidden behind HMMA)
        if (it + 1 < NIT) {
            int k0 = (it + 1) * KT;
#pragma unroll
            for (int i = 0; i < 4; i++) {
                int row = lrow + i * 32;
                regA[i] = *(const float4*)(A + (size_t)(m0 + row) * NN + k0 + lkq);
                regB[i] = *(const float4*)(Bt + (size_t)row * NN + k0 + lkq);
            }
        }

        // compute on stage s
        uint32_t aHi = sbase + s * STAGE_BYTES;
        uint32_t aLo = aHi + ARR_BYTES;
        uint32_t bHi = aHi + 2 * ARR_BYTES;
        uint32_t bLo = aHi + 3 * ARR_BYTES;
#pragma unroll
        for (int ks = 0; ks < 2; ks++) {
            int kb = ks * 16;
            uint32_t Ah[2][4], Al[2][4];
#pragma unroll
            for (int mt = 0; mt < 2; mt++) {
                uint32_t off = (uint32_t)((wm * 32 + mt * 16 + (g & 1) * 8 + r8) * ROWB
                                          + (kb + (g >> 1) * 8) * 2);
                ldsm_x4(Ah[mt], aHi + off);
                ldsm_x4(Al[mt], aLo + off);
            }
            uint32_t Bh[4][4], Bl[4][4];
#pragma unroll
            for (int p = 0; p < 4; p++) {
                uint32_t off = (uint32_t)((wn * 64 + p * 16 + ((g >> 1) & 1) * 8 + r8) * ROWB
                                          + (kb + (g & 1) * 8) * 2);
                ldsm_x4(Bh[p], bHi + off);
                ldsm_x4(Bl[p], bLo + off);
            }
#pragma unroll
            for (int mt = 0; mt < 2; mt++)
#pragma unroll
                for (int nt = 0; nt < 8; nt++) {
                    int p = nt >> 1;
                    int e = (nt & 1) * 2;
                    mma16816(acc[mt][nt], Ah[mt], &Bh[p][e]);   // hi*hi
                    mma16816(acc[mt][nt], Ah[mt], &Bl[p][e]);   // hi*lo
                    mma16816(acc[mt][nt], Al[mt], &Bh[p][e]);   // lo*hi
                }
        }

        // convert + store next stage
        if (it + 1 < NIT) {
            char* dsthi = smem + (s ^ 1) * STAGE_BYTES;
#pragma unroll
            for (int i = 0; i < 4; i++) {
                int row = lrow + i * 32;
                uint32_t off = row * ROWB + lkq * 2;
                uint2 hi, lo;
                cvt4(regA[i], hi, lo);
                *(uint2*)(dsthi + off) = hi;
                *(uint2*)(dsthi + ARR_BYTES + off) = lo;
                cvt4(regB[i], hi, lo);
                *(uint2*)(dsthi + 2 * ARR_BYTES + off) = hi;
                *(uint2*)(dsthi + 3 * ARR_BYTES + off) = lo;
            }
        }
        __syncthreads();
    }

    // ---- epilogue: ELU + store --------------------------------------------
    float* obase = (n0g < 256) ? out : (out + (size_t)BATCH * NN * FF);
    int nc0 = (n0g & 255) + wn * 64;
#pragma unroll
    for (int mt = 0; mt < 2; mt++) {
        int mrow = m0 + wm * 32 + mt * 16 + (lid >> 2);
#pragma unroll
        for (int nt = 0; nt < 8; nt++) {
            int col = nc0 + nt * 8 + 2 * (lid & 3);
            float* p0 = obase + (size_t)b * NN * FF + (size_t)mrow * FF + col;
            float2 v0 = { elu_f(acc[mt][nt][0]), elu_f(acc[mt][nt][1]) };
            *(float2*)p0 = v0;
            float* p1 = p0 + 8 * FF;
            float2 v1 = { elu_f(acc[mt][nt][2]), elu_f(acc[mt][nt][3]) };
            *(float2*)p1 = v1;
        }
    }
}

// ---------------------------------------------------------------------------
extern "C" void kernel_launch(void* const* d_in, const int* in_sizes, int n_in,
                              void* d_out, int out_size) {
    const float* h     = (const float*)d_in[0];
    const int*   adj   = (const int*)  d_in[1];
    const float* lrgt1 = (const float*)d_in[2];
    const float* W1    = (const float*)d_in[3];
    const float* W2    = (const float*)d_in[4];
    const float* a     = (const float*)d_in[5];
    float* out = (float*)d_out;

    float* BT;  cudaGetSymbolAddress((void**)&BT,  d_BT);
    float* s1;  cudaGetSymbolAddress((void**)&s1,  d_s1);
    float* s2;  cudaGetSymbolAddress((void**)&s2,  d_s2);
    float* v;   cudaGetSymbolAddress((void**)&v,   d_v);
    float* att; cudaGetSymbolAddress((void**)&att, d_att);

    v_kernel<<<1, 256>>>(W1, a, v);

    {
        dim3 grid(BN / 64, FF / 64, 2);
        feat_gemm<<<grid, 256>>>(h, lrgt1, W1, W2, BT);
    }

    scores_kernel<<<BN, 256>>>(h, v, s1, s2);
    softmax_kernel<<<BN, 256>>>(adj, s1, s2, att);

    {
        cudaFuncSetAttribute(attn_mma, cudaFuncAttributeMaxDynamicSharedMemorySize, SMEM_TOTAL);
        dim3 grid(NN / 128, NFEAT / 128, BATCH);
        attn_mma<<<grid, 256, SMEM_TOTAL>>>(att, BT, out);
    }
}

// round 4
// speedup vs baseline: 2.5555x; 1.2835x over previous
#include <cuda_runtime.h>
#include <cuda_bf16.h>
#include <cstdint>
#include <math.h>

#define BATCH 8
#define NN 2048
#define FF 256
#define NFEAT 512              // Wh (256) stacked with wl (256)
#define BN (BATCH * NN)        // 16384
#define ALPHA 0.2f

// ---------------- scratch (static device allocations; no cudaMalloc) --------
__device__ float d_BT[(size_t)BATCH * NFEAT * NN];   // 32 MB, [b][feat][node]
__device__ float d_s1[BN];
__device__ float d_s2[BN];
__device__ float d_v[2 * FF];
__device__ float d_att[(size_t)BATCH * NN * NN];     // 134 MB

// ---------------- kernel 1: v1 = W1 @ a[:F], v2 = W1 @ a[F:] ----------------
__global__ void v_kernel(const float* __restrict__ W1, const float* __restrict__ a,
                         float* __restrict__ v) {
    int k = threadIdx.x;
    float acc1 = 0.f, acc2 = 0.f;
    const float* wrow = W1 + (size_t)k * FF;
#pragma unroll 8
    for (int c = 0; c < FF; c++) {
        float w = wrow[c];
        acc1 += w * a[c];
        acc2 += w * a[FF + c];
    }
    v[k] = acc1;
    v[FF + k] = acc2;
}

// ---- kernel 2: BT[b][z*256+n][node] = (h@W1 / lr@W2)[b,node,n] (transposed) -
__global__ void feat_gemm(const float* __restrict__ h, const float* __restrict__ lr,
                          const float* __restrict__ W1, const float* __restrict__ W2,
                          float* __restrict__ BT) {
    const float* A;
    const float* W;
    int z = blockIdx.z;
    if (z == 0) { A = h;  W = W1; }
    else        { A = lr; W = W2; }

    int m0 = blockIdx.x * 64;
    int n0 = blockIdx.y * 64;
    __shared__ float As[16][66];
    __shared__ float Ws[16][64];
    __shared__ float Ct[64][65];

    int tid = threadIdx.x;
    int tx = tid & 15, ty = tid >> 4;
    float acc[4][4] = {};

    for (int k0 = 0; k0 < FF; k0 += 16) {
        {
            int row = tid >> 2;
            int kq = (tid & 3) * 4;
            float4 va = *(const float4*)(A + (size_t)(m0 + row) * FF + k0 + kq);
            As[kq + 0][row] = va.x; As[kq + 1][row] = va.y;
            As[kq + 2][row] = va.z; As[kq + 3][row] = va.w;
            int wr = tid >> 4;
            int c4 = (tid & 15) * 4;
            *(float4*)&Ws[wr][c4] = *(const float4*)(W + (size_t)(k0 + wr) * FF + n0 + c4);
        }
        __syncthreads();
#pragma unroll
        for (int kk = 0; kk < 16; kk++) {
            float av[4], bv[4];
#pragma unroll
            for (int i = 0; i < 4; i++) av[i] = As[kk][ty + 16 * i];
#pragma unroll
            for (int j = 0; j < 4; j++) bv[j] = Ws[kk][tx + 16 * j];
#pragma unroll
            for (int i = 0; i < 4; i++)
#pragma unroll
                for (int j = 0; j < 4; j++) acc[i][j] += av[i] * bv[j];
        }
        __syncthreads();
    }
#pragma unroll
    for (int i = 0; i < 4; i++)
#pragma unroll
        for (int j = 0; j < 4; j++)
            Ct[tx + 16 * j][ty + 16 * i] = acc[i][j];
    __syncthreads();
    int b = m0 >> 11;
    int node0 = m0 & (NN - 1);
    int fl = tid >> 2;
    int cs = (tid & 3) * 16;
    float* dst = BT + (size_t)b * NFEAT * NN + (size_t)(z * 256 + n0 + fl) * NN + node0 + cs;
#pragma unroll
    for (int c = 0; c < 16; c += 4) {
        float4 v;
        v.x = Ct[fl][cs + c]; v.y = Ct[fl][cs + c + 1];
        v.z = Ct[fl][cs + c + 2]; v.w = Ct[fl][cs + c + 3];
        *(float4*)(dst + c) = v;
    }
}

// ---------------- kernel 3: s1 = h.v1, s2 = h.v2 (exact fp32) ---------------
__global__ void scores_kernel(const float* __restrict__ h, const float* __restrict__ v,
                              float* __restrict__ s1, float* __restrict__ s2) {
    int r = blockIdx.x;
    int tid = threadIdx.x;
    float hv = h[(size_t)r * FF + tid];
    float p1 = hv * v[tid];
    float p2 = hv * v[FF + tid];
    __shared__ float r1[256];
    __shared__ float r2[256];
    r1[tid] = p1; r2[tid] = p2;
    __syncthreads();
    for (int s = 128; s > 0; s >>= 1) {
        if (tid < s) { r1[tid] += r1[tid + s]; r2[tid] += r2[tid + s]; }
        __syncthreads();
    }
    if (tid == 0) { s1[r] = r1[0]; s2[r] = r2[0]; }
}

// ---------------- kernel 4: masked leaky-relu softmax row -------------------
__global__ void softmax_kernel(const int* __restrict__ adj, const float* __restrict__ s1,
                               const float* __restrict__ s2, float* __restrict__ att) {
    int bi = blockIdx.x;
    int b = bi >> 11;
    const int* arow = adj + (size_t)bi * NN;
    const float* s2b = s2 + (size_t)b * NN;
    float si = s1[bi];

    __shared__ float x[NN];
    __shared__ float red[256];
    int tid = threadIdx.x;

    float lmax = -3.4e38f;
#pragma unroll
    for (int j = tid; j < NN; j += 256) {
        float val = si + s2b[j];
        val = val > 0.f ? val : ALPHA * val;
        val = arow[j] > 0 ? val : -9.0e15f;
        x[j] = val;
        lmax = fmaxf(lmax, val);
    }
    red[tid] = lmax;
    __syncthreads();
    for (int s = 128; s > 0; s >>= 1) {
        if (tid < s) red[tid] = fmaxf(red[tid], red[tid + s]);
        __syncthreads();
    }
    float m = red[0];
    __syncthreads();

    float lsum = 0.f;
#pragma unroll
    for (int j = tid; j < NN; j += 256) {
        float e = __expf(x[j] - m);
        x[j] = e;
        lsum += e;
    }
    red[tid] = lsum;
    __syncthreads();
    for (int s = 128; s > 0; s >>= 1) {
        if (tid < s) red[tid] += red[tid + s];
        __syncthreads();
    }
    float inv = 1.f / red[0];
    float* orow = att + (size_t)bi * NN;
#pragma unroll
    for (int j = tid; j < NN; j += 256) orow[j] = x[j] * inv;
}

// ======================= shared helpers =====================================
__device__ __forceinline__ uint32_t smem_u32(const void* p) {
    uint32_t a;
    asm("{ .reg .u64 t; cvta.to.shared.u64 t, %1; cvt.u32.u64 %0, t; }"
        : "=r"(a) : "l"(p));
    return a;
}
__device__ __forceinline__ float elu_f(float v) {
    return v > 0.f ? v : (expf(v) - 1.f);
}

// dynamic smem size: max of both paths (tcgen05 needs 1024 + 2*65536)
#define ATTN_SMEM_BYTES 132096

#if defined(__CUDA_ARCH__) && (defined(__CUDA_ARCH_FEAT_SM103_ALL) || defined(__CUDA_ARCH_FEAT_SM100_ALL) || defined(__CUDA_ARCH_FEAT_SM101_ALL))
#define HAS_TCGEN05 1
#else
#define HAS_TCGEN05 0
#endif

#if HAS_TCGEN05
// ================= tcgen05 path (sm_103a SASS) ==============================
__device__ __forceinline__ uint32_t elect_one_pred() {
    uint32_t pred;
    asm volatile(
        "{\n\t.reg .pred p;\n\telect.sync _|p, 0xFFFFFFFF;\n\t"
        "selp.b32 %0, 1, 0, p;\n\t}" : "=r"(pred));
    return pred;
}
#define MBARRIER_INIT(addr, cnt) \
    asm volatile("mbarrier.init.shared.b64 [%0], %1;" :: "r"((uint32_t)(addr)), "r"((uint32_t)(cnt)) : "memory")
#define MBARRIER_INVAL(addr) \
    asm volatile("mbarrier.inval.shared.b64 [%0];" :: "r"((uint32_t)(addr)) : "memory")
#define MBARRIER_WAIT_PARITY(mbar_smem_addr, phase_parity) do { \
    uint32_t _mbar = (uint32_t)(mbar_smem_addr); \
    uint32_t _parity = (uint32_t)(phase_parity); \
    uint32_t _done; \
    asm volatile( \
        "{\n\t.reg .pred p;\n\t" \
        "mbarrier.try_wait.parity.acquire.cta.shared::cta.b64 p, [%1], %2;\n\t" \
        "selp.b32 %0, 1, 0, p;\n\t}" \
        : "=r"(_done) : "r"(_mbar), "r"(_parity) : "memory"); \
    if (!_done) { \
        asm volatile( \
            "{\n\t.reg .pred P1;\n\t" \
            "WAIT_LOOP_%=:\n\t" \
            "mbarrier.try_wait.parity.acquire.cta.shared::cta.b64 P1, [%0], %1, 0x989680;\n\t" \
            "@P1 bra.uni WAIT_DONE_%=;\n\t" \
            "bra.uni WAIT_LOOP_%=;\n\t" \
            "WAIT_DONE_%=:\n\t}" \
            :: "r"(_mbar), "r"(_parity) : "memory"); \
    } \
} while (0)
#define TCGEN05_ALLOC(saddr, n) \
    asm volatile("tcgen05.alloc.cta_group::1.sync.aligned.shared::cta.b32 [%0], %1;" \
                 :: "r"((uint32_t)(saddr)), "r"((uint32_t)(n)) : "memory")
#define TCGEN05_DEALLOC(tm, n) \
    asm volatile("tcgen05.dealloc.cta_group::1.sync.aligned.b32 %0, %1;" :: "r"(tm), "r"((uint32_t)(n)))
#define TCGEN05_RELINQUISH() \
    asm volatile("tcgen05.relinquish_alloc_permit.cta_group::1.sync.aligned;")
#define TCGEN05_COMMIT(mbar) \
    asm volatile("tcgen05.commit.cta_group::1.mbarrier::arrive::one.shared::cluster.b64 [%0];" \
                 :: "r"((uint32_t)(mbar)) : "memory")
#define TCGEN05_FENCE_AFTER() asm volatile("tcgen05.fence::after_thread_sync;" ::: "memory")
#define TCGEN05_FENCE_BEFORE() asm volatile("tcgen05.fence::before_thread_sync;" ::: "memory")
#define TCGEN05_WAIT_LD() asm volatile("tcgen05.wait::ld.sync.aligned;" ::: "memory")
#define FENCE_PROXY_ASYNC() asm volatile("fence.proxy.async.shared::cta;" ::: "memory")
#define TCGEN05_LD_32X32B_X32(r, tmem_addr) \
    asm volatile( \
        "tcgen05.ld.sync.aligned.32x32b.x32.b32 " \
        "{%0, %1, %2, %3, %4, %5, %6, %7, " \
        " %8, %9, %10, %11, %12, %13, %14, %15, " \
        " %16, %17, %18, %19, %20, %21, %22, %23, " \
        " %24, %25, %26, %27, %28, %29, %30, %31}, [%32];" \
        : "=r"((r)[0]),  "=r"((r)[1]),  "=r"((r)[2]),  "=r"((r)[3]), \
          "=r"((r)[4]),  "=r"((r)[5]),  "=r"((r)[6]),  "=r"((r)[7]), \
          "=r"((r)[8]),  "=r"((r)[9]),  "=r"((r)[10]), "=r"((r)[11]), \
          "=r"((r)[12]), "=r"((r)[13]), "=r"((r)[14]), "=r"((r)[15]), \
          "=r"((r)[16]), "=r"((r)[17]), "=r"((r)[18]), "=r"((r)[19]), \
          "=r"((r)[20]), "=r"((r)[21]), "=r"((r)[22]), "=r"((r)[23]), \
          "=r"((r)[24]), "=r"((r)[25]), "=r"((r)[26]), "=r"((r)[27]), \
          "=r"((r)[28]), "=r"((r)[29]), "=r"((r)[30]), "=r"((r)[31]) \
        : "r"(tmem_addr))

static constexpr uint64_t SMEM_DESC_BASE_SW128 =
    (uint64_t(2) << 61) | (uint64_t(1) << 46) | (uint64_t(64) << 32) | (uint64_t(1) << 16);
#define MAKE_SMEM_DESC(base_addr) \
    (SMEM_DESC_BASE_SW128 | ((uint64_t)((base_addr) >> 4) & 0x3FFF))
#define SMEM_SWZ(o) ((o) ^ (((o) >> 3) & 0x70))

__device__ __forceinline__ void mma_bf16_ss(uint32_t d_tmem, uint64_t a_desc,
                                            uint64_t b_desc, uint32_t idesc, uint32_t en) {
    asm volatile(
        "{\n\t.reg .pred p;\n\tsetp.ne.u32 p, %4, 0;\n\t"
        "tcgen05.mma.cta_group::1.kind::f16 [%0], %1, %2, %3, {%5, %5, %5, %5}, p;\n\t}"
        :: "r"(d_tmem), "l"(a_desc), "l"(b_desc), "r"(idesc), "r"(en), "r"(0u)
        : "memory");
}
// idesc: f32 accum, bf16 a/b, N=128, M=128
static constexpr uint32_t MMA_IDESC =
    (1u << 4) | (1u << 7) | (1u << 10) | ((128u / 8) << 17) | ((128u / 16) << 24);

#define OFF_TMEM 0
#define OFF_MBAR 8
#define OFF_BUF  1024
#define T_STAGE_BYTES 65536

__device__ __forceinline__ void cvt4_store(char* hi, char* lo, uint32_t boff, float4 v) {
    union { __nv_bfloat16 h[4]; uint2 u; } H, L;
    H.h[0] = __float2bfloat16(v.x);
    H.h[1] = __float2bfloat16(v.y);
    H.h[2] = __float2bfloat16(v.z);
    H.h[3] = __float2bfloat16(v.w);
    L.h[0] = __float2bfloat16(v.x - __bfloat162float(H.h[0]));
    L.h[1] = __float2bfloat16(v.y - __bfloat162float(H.h[1]));
    L.h[2] = __float2bfloat16(v.z - __bfloat162float(H.h[2]));
    L.h[3] = __float2bfloat16(v.w - __bfloat162float(H.h[3]));
    uint32_t sw = SMEM_SWZ(boff);
    *(uint2*)(hi + sw) = H.u;
    *(uint2*)(lo + sw) = L.u;
}
#endif  // HAS_TCGEN05

#if !HAS_TCGEN05
// ================= HMMA fallback helpers ====================================
#define KT 32
#define ROWB 80
#define ARR_BYTES (128 * ROWB)
#define H_STAGE_BYTES (4 * ARR_BYTES)

__device__ __forceinline__ void ldsm_x4(uint32_t* r, uint32_t addr) {
    asm volatile("ldmatrix.sync.aligned.m8n8.x4.shared.b16 {%0,%1,%2,%3}, [%4];"
                 : "=r"(r[0]), "=r"(r[1]), "=r"(r[2]), "=r"(r[3]) : "r"(addr));
}
__device__ __forceinline__ void mma16816(float* d, const uint32_t* a, const uint32_t* b) {
    asm volatile(
        "mma.sync.aligned.m16n8k16.row.col.f32.bf16.bf16.f32 "
        "{%0,%1,%2,%3}, {%4,%5,%6,%7}, {%8,%9}, {%0,%1,%2,%3};"
        : "+f"(d[0]), "+f"(d[1]), "+f"(d[2]), "+f"(d[3])
        : "r"(a[0]), "r"(a[1]), "r"(a[2]), "r"(a[3]), "r"(b[0]), "r"(b[1]));
}
__device__ __forceinline__ void cvt4h(float4 v, uint2& hi, uint2& lo) {
    union { __nv_bfloat16 h[4]; uint2 u; } H, L;
    H.h[0] = __float2bfloat16(v.x);
    H.h[1] = __float2bfloat16(v.y);
    H.h[2] = __float2bfloat16(v.z);
    H.h[3] = __float2bfloat16(v.w);
    L.h[0] = __float2bfloat16(v.x - __bfloat162float(H.h[0]));
    L.h[1] = __float2bfloat16(v.y - __bfloat162float(H.h[1]));
    L.h[2] = __float2bfloat16(v.z - __bfloat162float(H.h[2]));
    L.h[3] = __float2bfloat16(v.w - __bfloat162float(H.h[3]));
    hi = H.u; lo = L.u;
}
#endif  // !HAS_TCGEN05

// ============== kernel 5: dual GEMM att@[Wh|wl] + ELU =======================
__global__ void __launch_bounds__(256, 1)
attn_mma(const float* __restrict__ att, const float* __restrict__ BT,
         float* __restrict__ out) {
    extern __shared__ char smem[];
    const int tid = threadIdx.x;
    const int wid = tid >> 5;
    const int lid = tid & 31;
    const int b = blockIdx.z;
    const int m0 = blockIdx.x * 128;
    const int n0g = blockIdx.y * 128;
    const float* A  = att + (size_t)b * NN * NN;
    const float* Bt = BT + (size_t)b * NFEAT * NN + (size_t)n0g * NN;

#if HAS_TCGEN05
    // ---------------- tcgen05 pipeline --------------------------------------
    uint32_t sbase = smem_u32(smem);
    if (wid == 0) TCGEN05_ALLOC(sbase + OFF_TMEM, 128);
    if (tid == 0) {
        MBARRIER_INIT(sbase + OFF_MBAR, 1);
        MBARRIER_INIT(sbase + OFF_MBAR + 8, 1);
    }
    __syncthreads();
    uint32_t tmem;
    asm volatile("ld.shared.b32 %0, [%1];" : "=r"(tmem) : "r"(sbase + OFF_TMEM));

    auto load_stage = [&](int s, int k0) {
        char* base = smem + OFF_BUF + s * T_STAGE_BYTES;
        char* Ahi = base;
        char* Alo = base + 16384;
        char* Bhi = base + 32768;
        char* Blo = base + 49152;
        // batch the 16 global loads first for MLP, then convert+store
        float4 va[8], vb[8];
#pragma unroll
        for (int i = 0; i < 8; i++) {
            int idx = tid + i * 256;
            int row = idx >> 4;
            int kq  = (idx & 15) * 4;
            va[i] = *(const float4*)(A + (size_t)(m0 + row) * NN + k0 + kq);
            vb[i] = *(const float4*)(Bt + (size_t)row * NN + k0 + kq);
        }
#pragma unroll
        for (int i = 0; i < 8; i++) {
            int idx = tid + i * 256;
            int row = idx >> 4;
            int kq  = (idx & 15) * 4;
            uint32_t boff = (uint32_t)(row * 128 + kq * 2);
            cvt4_store(Ahi, Alo, boff, va[i]);
            cvt4_store(Bhi, Blo, boff, vb[i]);
        }
    };

    const int NIT = NN / 64;   // 32
    load_stage(0, 0);
    __syncthreads();

    int ph[2] = {0, 0};
    for (int it = 0; it < NIT; it++) {
        int s = it & 1;
        if (wid == 0) {
            FENCE_PROXY_ASYNC();
            if (elect_one_pred()) {
                uint32_t sb = sbase + OFF_BUF + s * T_STAGE_BYTES;
                uint64_t dA[2] = { MAKE_SMEM_DESC(sb),         MAKE_SMEM_DESC(sb + 16384) };
                uint64_t dB[2] = { MAKE_SMEM_DESC(sb + 32768), MAKE_SMEM_DESC(sb + 49152) };
#pragma unroll
                for (int p = 0; p < 3; p++) {     // hi*hi, hi*lo, lo*hi
                    int ai = (p == 2) ? 1 : 0;
                    int bi2 = (p == 1) ? 1 : 0;
#pragma unroll
                    for (int ks = 0; ks < 4; ks++) {
                        uint32_t en = !(it == 0 && p == 0 && ks == 0);
                        mma_bf16_ss(tmem, dA[ai] + ks * 2, dB[bi2] + ks * 2, MMA_IDESC, en);
                    }
                }
                TCGEN05_COMMIT(sbase + OFF_MBAR + s * 8);
            }
        }
        if (it + 1 < NIT) {
            if (it >= 1) {
                int so = s ^ 1;
                MBARRIER_WAIT_PARITY(sbase + OFF_MBAR + so * 8, ph[so]);
                ph[so] ^= 1;
            }
            load_stage(s ^ 1, (it + 1) * 64);
        }
        __syncthreads();
    }
    {
        int sl = (NIT - 1) & 1;
        MBARRIER_WAIT_PARITY(sbase + OFF_MBAR + (sl ^ 1) * 8, ph[sl ^ 1]);
        MBARRIER_WAIT_PARITY(sbase + OFF_MBAR + sl * 8, ph[sl]);
    }
    TCGEN05_FENCE_AFTER();

    {
        int sp = wid & 3;
        int half = wid >> 2;
        uint32_t dr[64];
        TCGEN05_LD_32X32B_X32(dr, tmem + half * 64);
        TCGEN05_LD_32X32B_X32(dr + 32, tmem + half * 64 + 32);
        TCGEN05_WAIT_LD();
        TCGEN05_FENCE_BEFORE();

        int m = m0 + sp * 32 + lid;
        float* obase = (n0g < 256) ? out : (out + (size_t)BATCH * NN * FF);
        int nc0 = (n0g & 255) + half * 64;
        float* orow = obase + (size_t)b * NN * FF + (size_t)m * FF + nc0;
#pragma unroll
        for (int c = 0; c < 64; c += 4) {
            float4 o;
            o.x = elu_f(__uint_as_float(dr[c + 0]));
            o.y = elu_f(__uint_as_float(dr[c + 1]));
            o.z = elu_f(__uint_as_float(dr[c + 2]));
            o.w = elu_f(__uint_as_float(dr[c + 3]));
            *(float4*)(orow + c) = o;
        }
    }

    __syncthreads();
    if (tid == 0) { MBARRIER_INVAL(sbase + OFF_MBAR); MBARRIER_INVAL(sbase + OFF_MBAR + 8); }
    __syncthreads();
    if (wid == 0) {
        TCGEN05_RELINQUISH();
        TCGEN05_DEALLOC(tmem, 128);
    }
#else
    // ---------------- HMMA fallback (proven R3 body) ------------------------
    const uint32_t sbase = smem_u32(smem);
    const int wm = wid & 3;
    const int wn = wid >> 2;
    const int g  = lid >> 3;
    const int r8 = lid & 7;
    const int lrow = tid >> 3;
    const int lkq  = (tid & 7) * 4;

    float acc[2][8][4] = {};
    float4 regA[4], regB[4];

    {
        char* dsthi = smem;
#pragma unroll
        for (int i = 0; i < 4; i++) {
            int row = lrow + i * 32;
            float4 va = *(const float4*)(A + (size_t)(m0 + row) * NN + lkq);
            float4 vb = *(const float4*)(Bt + (size_t)row * NN + lkq);
            uint2 hi, lo;
            uint32_t off = row * ROWB + lkq * 2;
            cvt4h(va, hi, lo);
            *(uint2*)(dsthi + off) = hi;
            *(uint2*)(dsthi + ARR_BYTES + off) = lo;
            cvt4h(vb, hi, lo);
            *(uint2*)(dsthi + 2 * ARR_BYTES + off) = hi;
            *(uint2*)(dsthi + 3 * ARR_BYTES + off) = lo;
        }
    }
    __syncthreads();

    const int NIT = NN / KT;   // 64
    for (int it = 0; it < NIT; it++) {
        int s = it & 1;
        if (it + 1 < NIT) {
            int k0 = (it + 1) * KT;
#pragma unroll
            for (int i = 0; i < 4; i++) {
                int row = lrow + i * 32;
                regA[i] = *(const float4*)(A + (size_t)(m0 + row) * NN + k0 + lkq);
                regB[i] = *(const float4*)(Bt + (size_t)row * NN + k0 + lkq);
            }
        }

        uint32_t aHi = sbase + s * H_STAGE_BYTES;
        uint32_t aLo = aHi + ARR_BYTES;
        uint32_t bHi = aHi + 2 * ARR_BYTES;
        uint32_t bLo = aHi + 3 * ARR_BYTES;
#pragma unroll
        for (int ks = 0; ks < 2; ks++) {
            int kb = ks * 16;
            uint32_t Ah[2][4], Al[2][4];
#pragma unroll
            for (int mt = 0; mt < 2; mt++) {
                uint32_t off = (uint32_t)((wm * 32 + mt * 16 + (g & 1) * 8 + r8) * ROWB
                                          + (kb + (g >> 1) * 8) * 2);
                ldsm_x4(Ah[mt], aHi + off);
                ldsm_x4(Al[mt], aLo + off);
            }
            uint32_t Bh[4][4], Bl[4][4];
#pragma unroll
            for (int p = 0; p < 4; p++) {
                uint32_t off = (uint32_t)((wn * 64 + p * 16 + ((g >> 1) & 1) * 8 + r8) * ROWB
                                          + (kb + (g & 1) * 8) * 2);
                ldsm_x4(Bh[p], bHi + off);
                ldsm_x4(Bl[p], bLo + off);
            }
#pragma unroll
            for (int mt = 0; mt < 2; mt++)
#pragma unroll
                for (int nt = 0; nt < 8; nt++) {
                    int p = nt >> 1;
                    int e = (nt & 1) * 2;
                    mma16816(acc[mt][nt], Ah[mt], &Bh[p][e]);
                    mma16816(acc[mt][nt], Ah[mt], &Bl[p][e]);
                    mma16816(acc[mt][nt], Al[mt], &Bh[p][e]);
                }
        }

        if (it + 1 < NIT) {
            char* dsthi = smem + (s ^ 1) * H_STAGE_BYTES;
#pragma unroll
            for (int i = 0; i < 4; i++) {
                int row = lrow + i * 32;
                uint32_t off = row * ROWB + lkq * 2;
                uint2 hi, lo;
                cvt4h(regA[i], hi, lo);
                *(uint2*)(dsthi + off) = hi;
                *(uint2*)(dsthi + ARR_BYTES + off) = lo;
                cvt4h(regB[i], hi, lo);
                *(uint2*)(dsthi + 2 * ARR_BYTES + off) = hi;
                *(uint2*)(dsthi + 3 * ARR_BYTES + off) = lo;
            }
        }
        __syncthreads();
    }

    float* obase = (n0g < 256) ? out : (out + (size_t)BATCH * NN * FF);
    int nc0 = (n0g & 255) + wn * 64;
#pragma unroll
    for (int mt = 0; mt < 2; mt++) {
        int mrow = m0 + wm * 32 + mt * 16 + (lid >> 2);
#pragma unroll
        for (int nt = 0; nt < 8; nt++) {
            int col = nc0 + nt * 8 + 2 * (lid & 3);
            float* p0 = obase + (size_t)b * NN * FF + (size_t)mrow * FF + col;
            float2 v0 = { elu_f(acc[mt][nt][0]), elu_f(acc[mt][nt][1]) };
            *(float2*)p0 = v0;
            float* p1 = p0 + 8 * FF;
            float2 v1 = { elu_f(acc[mt][nt][2]), elu_f(acc[mt][nt][3]) };
            *(float2*)p1 = v1;
        }
    }
#endif
}

// ---------------------------------------------------------------------------
extern "C" void kernel_launch(void* const* d_in, const int* in_sizes, int n_in,
                              void* d_out, int out_size) {
    const float* h     = (const float*)d_in[0];
    const int*   adj   = (const int*)  d_in[1];
    const float* lrgt1 = (const float*)d_in[2];
    const float* W1    = (const float*)d_in[3];
    const float* W2    = (const float*)d_in[4];
    const float* a     = (const float*)d_in[5];
    float* out = (float*)d_out;

    float* BT;  cudaGetSymbolAddress((void**)&BT,  d_BT);
    float* s1;  cudaGetSymbolAddress((void**)&s1,  d_s1);
    float* s2;  cudaGetSymbolAddress((void**)&s2,  d_s2);
    float* v;   cudaGetSymbolAddress((void**)&v,   d_v);
    float* att; cudaGetSymbolAddress((void**)&att, d_att);

    v_kernel<<<1, 256>>>(W1, a, v);

    {
        dim3 grid(BN / 64, FF / 64, 2);
        feat_gemm<<<grid, 256>>>(h, lrgt1, W1, W2, BT);
    }

    scores_kernel<<<BN, 256>>>(h, v, s1, s2);
    softmax_kernel<<<BN, 256>>>(adj, s1, s2, att);

    {
        cudaFuncSetAttribute(attn_mma, cudaFuncAttributeMaxDynamicSharedMemorySize, ATTN_SMEM_BYTES);
        dim3 grid(NN / 128, NFEAT / 128, BATCH);
        attn_mma<<<grid, 256, ATTN_SMEM_BYTES>>>(att, BT, out);
    }
}

// round 5
// speedup vs baseline: 3.2502x; 1.2719x over previous
#include <cuda_runtime.h>
#include <cuda_bf16.h>
#include <cstdint>
#include <math.h>

#define BATCH 8
#define NN 2048
#define FF 256
#define NFEAT 512              // Wh (256) stacked with wl (256)
#define BN (BATCH * NN)        // 16384
#define ALPHA 0.2f

// ---------------- scratch (static device allocations; no cudaMalloc) --------
__device__ __nv_bfloat16 d_att_hi[(size_t)BATCH * NN * NN];  // 67 MB
__device__ __nv_bfloat16 d_att_lo[(size_t)BATCH * NN * NN];  // 67 MB
__device__ __nv_bfloat16 d_bth[(size_t)BATCH * NFEAT * NN];  // 16 MB
__device__ __nv_bfloat16 d_btl[(size_t)BATCH * NFEAT * NN];  // 16 MB
__device__ float d_s1[BN];
__device__ float d_s2[BN];
__device__ float d_v[2 * FF];

// ---------------- kernel 1: v1 = W1 @ a[:F], v2 = W1 @ a[F:] ----------------
__global__ void v_kernel(const float* __restrict__ W1, const float* __restrict__ a,
                         float* __restrict__ v) {
    int k = threadIdx.x;
    float acc1 = 0.f, acc2 = 0.f;
    const float* wrow = W1 + (size_t)k * FF;
#pragma unroll 8
    for (int c = 0; c < FF; c++) {
        float w = wrow[c];
        acc1 += w * a[c];
        acc2 += w * a[FF + c];
    }
    v[k] = acc1;
    v[FF + k] = acc2;
}

// ---- kernel 2: BT hi/lo [b][z*256+n][node] = split((h@W1 / lr@W2)^T) -------
__global__ void feat_gemm(const float* __restrict__ h, const float* __restrict__ lr,
                          const float* __restrict__ W1, const float* __restrict__ W2,
                          __nv_bfloat16* __restrict__ BTh, __nv_bfloat16* __restrict__ BTl) {
    const float* A;
    const float* W;
    int z = blockIdx.z;
    if (z == 0) { A = h;  W = W1; }
    else        { A = lr; W = W2; }

    int m0 = blockIdx.x * 64;
    int n0 = blockIdx.y * 64;
    __shared__ float As[16][66];
    __shared__ float Ws[16][64];
    __shared__ float Ct[64][65];

    int tid = threadIdx.x;
    int tx = tid & 15, ty = tid >> 4;
    float acc[4][4] = {};

    for (int k0 = 0; k0 < FF; k0 += 16) {
        {
            int row = tid >> 2;
            int kq = (tid & 3) * 4;
            float4 va = *(const float4*)(A + (size_t)(m0 + row) * FF + k0 + kq);
            As[kq + 0][row] = va.x; As[kq + 1][row] = va.y;
            As[kq + 2][row] = va.z; As[kq + 3][row] = va.w;
            int wr = tid >> 4;
            int c4 = (tid & 15) * 4;
            *(float4*)&Ws[wr][c4] = *(const float4*)(W + (size_t)(k0 + wr) * FF + n0 + c4);
        }
        __syncthreads();
#pragma unroll
        for (int kk = 0; kk < 16; kk++) {
            float av[4], bv[4];
#pragma unroll
            for (int i = 0; i < 4; i++) av[i] = As[kk][ty + 16 * i];
#pragma unroll
            for (int j = 0; j < 4; j++) bv[j] = Ws[kk][tx + 16 * j];
#pragma unroll
            for (int i = 0; i < 4; i++)
#pragma unroll
                for (int j = 0; j < 4; j++) acc[i][j] += av[i] * bv[j];
        }
        __syncthreads();
    }
#pragma unroll
    for (int i = 0; i < 4; i++)
#pragma unroll
        for (int j = 0; j < 4; j++)
            Ct[tx + 16 * j][ty + 16 * i] = acc[i][j];
    __syncthreads();
    int b = m0 >> 11;
    int node0 = m0 & (NN - 1);
    int fl = tid >> 2;
    int cs = (tid & 3) * 16;
    size_t base = (size_t)b * NFEAT * NN + (size_t)(z * 256 + n0 + fl) * NN + node0 + cs;
    __nv_bfloat16* dh = BTh + base;
    __nv_bfloat16* dl = BTl + base;
#pragma unroll
    for (int c = 0; c < 16; c += 4) {
        union { __nv_bfloat16 h[4]; uint2 u; } H, L;
#pragma unroll
        for (int q = 0; q < 4; q++) {
            float p = Ct[fl][cs + c + q];
            H.h[q] = __float2bfloat16(p);
            L.h[q] = __float2bfloat16(p - __bfloat162float(H.h[q]));
        }
        *(uint2*)(dh + c) = H.u;
        *(uint2*)(dl + c) = L.u;
    }
}

// ---------------- kernel 3: s1 = h.v1, s2 = h.v2 (exact fp32) ---------------
__global__ void scores_kernel(const float* __restrict__ h, const float* __restrict__ v,
                              float* __restrict__ s1, float* __restrict__ s2) {
    int r = blockIdx.x;
    int tid = threadIdx.x;
    float hv = h[(size_t)r * FF + tid];
    float p1 = hv * v[tid];
    float p2 = hv * v[FF + tid];
    __shared__ float r1[256];
    __shared__ float r2[256];
    r1[tid] = p1; r2[tid] = p2;
    __syncthreads();
    for (int s = 128; s > 0; s >>= 1) {
        if (tid < s) { r1[tid] += r1[tid + s]; r2[tid] += r2[tid + s]; }
        __syncthreads();
    }
    if (tid == 0) { s1[r] = r1[0]; s2[r] = r2[0]; }
}

// --------- kernel 4: masked leaky-relu softmax -> bf16 hi/lo split ----------
__global__ void softmax_kernel(const int* __restrict__ adj, const float* __restrict__ s1,
                               const float* __restrict__ s2,
                               __nv_bfloat16* __restrict__ att_hi,
                               __nv_bfloat16* __restrict__ att_lo) {
    int bi = blockIdx.x;
    int b = bi >> 11;
    const int4* arow = (const int4*)(adj + (size_t)bi * NN);
    const float4* s2b = (const float4*)(s2 + (size_t)b * NN);
    float si = s1[bi];

    __shared__ float x[NN];
    __shared__ float redm[8];
    __shared__ float reds[8];
    int tid = threadIdx.x;
    int lane = tid & 31, warp = tid >> 5;

    float lmax = -3.4e38f;
#pragma unroll
    for (int c = 0; c < 2; c++) {
        int j4 = tid + c * 256;
        int4 av = arow[j4];
        float4 sv = s2b[j4];
        float v0 = si + sv.x; v0 = v0 > 0.f ? v0 : ALPHA * v0; v0 = av.x > 0 ? v0 : -9.0e15f;
        float v1 = si + sv.y; v1 = v1 > 0.f ? v1 : ALPHA * v1; v1 = av.y > 0 ? v1 : -9.0e15f;
        float v2 = si + sv.z; v2 = v2 > 0.f ? v2 : ALPHA * v2; v2 = av.z > 0 ? v2 : -9.0e15f;
        float v3 = si + sv.w; v3 = v3 > 0.f ? v3 : ALPHA * v3; v3 = av.w > 0 ? v3 : -9.0e15f;
        int j = j4 * 4;
        x[j] = v0; x[j + 1] = v1; x[j + 2] = v2; x[j + 3] = v3;
        lmax = fmaxf(fmaxf(fmaxf(lmax, v0), fmaxf(v1, v2)), v3);
    }
#pragma unroll
    for (int o = 16; o; o >>= 1) lmax = fmaxf(lmax, __shfl_xor_sync(0xffffffffu, lmax, o));
    if (lane == 0) redm[warp] = lmax;
    __syncthreads();
    float m = redm[0];
#pragma unroll
    for (int w = 1; w < 8; w++) m = fmaxf(m, redm[w]);

    float lsum = 0.f;
#pragma unroll
    for (int c = 0; c < 2; c++) {
        int j = (tid + c * 256) * 4;
        float e0 = __expf(x[j] - m);
        float e1 = __expf(x[j + 1] - m);
        float e2 = __expf(x[j + 2] - m);
        float e3 = __expf(x[j + 3] - m);
        x[j] = e0; x[j + 1] = e1; x[j + 2] = e2; x[j + 3] = e3;
        lsum += (e0 + e1) + (e2 + e3);
    }
#pragma unroll
    for (int o = 16; o; o >>= 1) lsum += __shfl_xor_sync(0xffffffffu, lsum, o);
    if (lane == 0) reds[warp] = lsum;
    __syncthreads();
    float tot = 0.f;
#pragma unroll
    for (int w = 0; w < 8; w++) tot += reds[w];
    float inv = 1.f / tot;

    uint2* oh = (uint2*)(att_hi + (size_t)bi * NN);
    uint2* ol = (uint2*)(att_lo + (size_t)bi * NN);
#pragma unroll
    for (int c = 0; c < 2; c++) {
        int j4 = tid + c * 256;
        int j = j4 * 4;
        union { __nv_bfloat16 h[4]; uint2 u; } H, L;
#pragma unroll
        for (int q = 0; q < 4; q++) {
            float p = x[j + q] * inv;
            H.h[q] = __float2bfloat16(p);
            L.h[q] = __float2bfloat16(p - __bfloat162float(H.h[q]));
        }
        oh[j4] = H.u;
        ol[j4] = L.u;
    }
}

// ======================= shared helpers =====================================
__device__ __forceinline__ uint32_t smem_u32(const void* p) {
    uint32_t a;
    asm("{ .reg .u64 t; cvta.to.shared.u64 t, %1; cvt.u32.u64 %0, t; }"
        : "=r"(a) : "l"(p));
    return a;
}
__device__ __forceinline__ float elu_f(float v) {
    return v > 0.f ? v : (expf(v) - 1.f);
}

#define ATTN_SMEM_BYTES 197632   // 1024 + 3 * 65536

#if defined(__CUDA_ARCH__) && (defined(__CUDA_ARCH_FEAT_SM103_ALL) || defined(__CUDA_ARCH_FEAT_SM100_ALL) || defined(__CUDA_ARCH_FEAT_SM101_ALL))
#define HAS_TCGEN05 1
#else
#define HAS_TCGEN05 0
#endif

#if HAS_TCGEN05
// ================= tcgen05 path (sm_103a SASS) ==============================
__device__ __forceinline__ uint32_t elect_one_pred() {
    uint32_t pred;
    asm volatile(
        "{\n\t.reg .pred p;\n\telect.sync _|p, 0xFFFFFFFF;\n\t"
        "selp.b32 %0, 1, 0, p;\n\t}" : "=r"(pred));
    return pred;
}
#define MBARRIER_INIT(addr, cnt) \
    asm volatile("mbarrier.init.shared.b64 [%0], %1;" :: "r"((uint32_t)(addr)), "r"((uint32_t)(cnt)) : "memory")
#define MBARRIER_INVAL(addr) \
    asm volatile("mbarrier.inval.shared.b64 [%0];" :: "r"((uint32_t)(addr)) : "memory")
#define MBARRIER_WAIT_PARITY(mbar_smem_addr, phase_parity) do { \
    uint32_t _mbar = (uint32_t)(mbar_smem_addr); \
    uint32_t _parity = (uint32_t)(phase_parity); \
    uint32_t _done; \
    asm volatile( \
        "{\n\t.reg .pred p;\n\t" \
        "mbarrier.try_wait.parity.acquire.cta.shared::cta.b64 p, [%1], %2;\n\t" \
        "selp.b32 %0, 1, 0, p;\n\t}" \
        : "=r"(_done) : "r"(_mbar), "r"(_parity) : "memory"); \
    if (!_done) { \
        asm volatile( \
            "{\n\t.reg .pred P1;\n\t" \
            "WAIT_LOOP_%=:\n\t" \
            "mbarrier.try_wait.parity.acquire.cta.shared::cta.b64 P1, [%0], %1, 0x989680;\n\t" \
            "@P1 bra.uni WAIT_DONE_%=;\n\t" \
            "bra.uni WAIT_LOOP_%=;\n\t" \
            "WAIT_DONE_%=:\n\t}" \
            :: "r"(_mbar), "r"(_parity) : "memory"); \
    } \
} while (0)
#define TCGEN05_ALLOC(saddr, n) \
    asm volatile("tcgen05.alloc.cta_group::1.sync.aligned.shared::cta.b32 [%0], %1;" \
                 :: "r"((uint32_t)(saddr)), "r"((uint32_t)(n)) : "memory")
#define TCGEN05_DEALLOC(tm, n) \
    asm volatile("tcgen05.dealloc.cta_group::1.sync.aligned.b32 %0, %1;" :: "r"(tm), "r"((uint32_t)(n)))
#define TCGEN05_RELINQUISH() \
    asm volatile("tcgen05.relinquish_alloc_permit.cta_group::1.sync.aligned;")
#define TCGEN05_COMMIT(mbar) \
    asm volatile("tcgen05.commit.cta_group::1.mbarrier::arrive::one.shared::cluster.b64 [%0];" \
                 :: "r"((uint32_t)(mbar)) : "memory")
#define TCGEN05_FENCE_AFTER() asm volatile("tcgen05.fence::after_thread_sync;" ::: "memory")
#define TCGEN05_FENCE_BEFORE() asm volatile("tcgen05.fence::before_thread_sync;" ::: "memory")
#define TCGEN05_WAIT_LD() asm volatile("tcgen05.wait::ld.sync.aligned;" ::: "memory")
#define FENCE_PROXY_ASYNC() asm volatile("fence.proxy.async.shared::cta;" ::: "memory")
#define CP_ASYNC16(dst, src) \
    asm volatile("cp.async.cg.shared.global [%0], [%1], 16;" :: "r"((uint32_t)(dst)), "l"(src) : "memory")
#define CP_COMMIT() asm volatile("cp.async.commit_group;" ::: "memory")
#define CP_WAIT(n)  asm volatile("cp.async.wait_group %0;" :: "n"(n) : "memory")
#define TCGEN05_LD_32X32B_X32(r, tmem_addr) \
    asm volatile( \
        "tcgen05.ld.sync.aligned.32x32b.x32.b32 " \
        "{%0, %1, %2, %3, %4, %5, %6, %7, " \
        " %8, %9, %10, %11, %12, %13, %14, %15, " \
        " %16, %17, %18, %19, %20, %21, %22, %23, " \
        " %24, %25, %26, %27, %28, %29, %30, %31}, [%32];" \
        : "=r"((r)[0]),  "=r"((r)[1]),  "=r"((r)[2]),  "=r"((r)[3]), \
          "=r"((r)[4]),  "=r"((r)[5]),  "=r"((r)[6]),  "=r"((r)[7]), \
          "=r"((r)[8]),  "=r"((r)[9]),  "=r"((r)[10]), "=r"((r)[11]), \
          "=r"((r)[12]), "=r"((r)[13]), "=r"((r)[14]), "=r"((r)[15]), \
          "=r"((r)[16]), "=r"((r)[17]), "=r"((r)[18]), "=r"((r)[19]), \
          "=r"((r)[20]), "=r"((r)[21]), "=r"((r)[22]), "=r"((r)[23]), \
          "=r"((r)[24]), "=r"((r)[25]), "=r"((r)[26]), "=r"((r)[27]), \
          "=r"((r)[28]), "=r"((r)[29]), "=r"((r)[30]), "=r"((r)[31]) \
        : "r"(tmem_addr))

static constexpr uint64_t SMEM_DESC_BASE_SW128 =
    (uint64_t(2) << 61) | (uint64_t(1) << 46) | (uint64_t(64) << 32) | (uint64_t(1) << 16);
#define MAKE_SMEM_DESC(base_addr) \
    (SMEM_DESC_BASE_SW128 | ((uint64_t)((base_addr) >> 4) & 0x3FFF))
#define SMEM_SWZ(o) ((o) ^ (((o) >> 3) & 0x70))

__device__ __forceinline__ void mma_bf16_ss(uint32_t d_tmem, uint64_t a_desc,
                                            uint64_t b_desc, uint32_t idesc, uint32_t en) {
    asm volatile(
        "{\n\t.reg .pred p;\n\tsetp.ne.u32 p, %4, 0;\n\t"
        "tcgen05.mma.cta_group::1.kind::f16 [%0], %1, %2, %3, {%5, %5, %5, %5}, p;\n\t}"
        :: "r"(d_tmem), "l"(a_desc), "l"(b_desc), "r"(idesc), "r"(en), "r"(0u)
        : "memory");
}
// idesc: f32 accum, bf16 a/b, N=128, M=128
static constexpr uint32_t MMA_IDESC =
    (1u << 4) | (1u << 7) | (1u << 10) | ((128u / 8) << 17) | ((128u / 16) << 24);

#define OFF_TMEM 0
#define OFF_MBAR 8
#define OFF_BUF  1024
#define T_STAGE_BYTES 65536
#endif  // HAS_TCGEN05

// ============== kernel 5: dual GEMM att@[Wh|wl] + ELU =======================
__global__ void __launch_bounds__(256, 1)
attn_mma(const __nv_bfloat16* __restrict__ att_hi, const __nv_bfloat16* __restrict__ att_lo,
         const __nv_bfloat16* __restrict__ BTh, const __nv_bfloat16* __restrict__ BTl,
         float* __restrict__ out) {
    extern __shared__ char smem[];
    const int tid = threadIdx.x;
    const int wid = tid >> 5;
    const int lid = tid & 31;
    const int b = blockIdx.z;
    const int m0 = blockIdx.x * 128;
    const int n0g = blockIdx.y * 128;
    const __nv_bfloat16* Ah = att_hi + (size_t)b * NN * NN;
    const __nv_bfloat16* Al = att_lo + (size_t)b * NN * NN;
    const __nv_bfloat16* Bh = BTh + (size_t)b * NFEAT * NN + (size_t)n0g * NN;
    const __nv_bfloat16* Bl = BTl + (size_t)b * NFEAT * NN + (size_t)n0g * NN;

#if HAS_TCGEN05
    uint32_t sbase = smem_u32(smem);
    if (wid == 0) TCGEN05_ALLOC(sbase + OFF_TMEM, 128);
    if (tid == 0) {
        MBARRIER_INIT(sbase + OFF_MBAR, 1);
        MBARRIER_INIT(sbase + OFF_MBAR + 8, 1);
        MBARRIER_INIT(sbase + OFF_MBAR + 16, 1);
    }
    __syncthreads();
    uint32_t tmem;
    asm volatile("ld.shared.b32 %0, [%1];" : "=r"(tmem) : "r"(sbase + OFF_TMEM));

    // cp.async stage loader: 16 x 16B per thread -> Ahi|Alo|Bhi|Blo (SW128)
    auto issue_loads = [&](int it) {
        int s = it % 3;
        int k0 = it * 64;
        uint32_t sb = sbase + OFF_BUF + s * T_STAGE_BYTES;
#pragma unroll
        for (int i = 0; i < 4; i++) {
            int idx = tid + i * 256;          // 0..1023
            int row = idx >> 3;               // 0..127
            int kc  = (idx & 7) * 8;          // bf16 col 0..56
            uint32_t doff = SMEM_SWZ((uint32_t)(row * 128 + kc * 2));
            const __nv_bfloat16* pa = Ah + (size_t)(m0 + row) * NN + k0 + kc;
            const __nv_bfloat16* pl = Al + (size_t)(m0 + row) * NN + k0 + kc;
            const __nv_bfloat16* pb = Bh + (size_t)row * NN + k0 + kc;
            const __nv_bfloat16* pc = Bl + (size_t)row * NN + k0 + kc;
            CP_ASYNC16(sb + doff,            pa);
            CP_ASYNC16(sb + 16384 + doff,    pl);
            CP_ASYNC16(sb + 32768 + doff,    pb);
            CP_ASYNC16(sb + 49152 + doff,    pc);
        }
    };

    const int NIT = NN / 64;   // 32
    issue_loads(0); CP_COMMIT();
    issue_loads(1); CP_COMMIT();

    int ph[3] = {0, 0, 0};
    for (int it = 0; it < NIT; it++) {
        int s = it % 3;
        // prefetch stage it+2 (slot guarded by MMA(it-1) completion)
        if (it + 2 < NIT) {
            if (it >= 1) {
                int so = (it - 1) % 3;
                MBARRIER_WAIT_PARITY(sbase + OFF_MBAR + so * 8, ph[so]);
                ph[so] ^= 1;
            }
            issue_loads(it + 2);
            CP_COMMIT();
        }
        // ensure stage it landed
        if (it + 2 < NIT)      { CP_WAIT(2); }
        else if (it + 1 < NIT) { CP_WAIT(1); }
        else                   { CP_WAIT(0); }
        __syncthreads();

        if (wid == 0) {
            FENCE_PROXY_ASYNC();
            if (elect_one_pred()) {
                uint32_t sb = sbase + OFF_BUF + s * T_STAGE_BYTES;
                uint64_t dA[2] = { MAKE_SMEM_DESC(sb),         MAKE_SMEM_DESC(sb + 16384) };
                uint64_t dB[2] = { MAKE_SMEM_DESC(sb + 32768), MAKE_SMEM_DESC(sb + 49152) };
#pragma unroll
                for (int p = 0; p < 3; p++) {     // hi*hi, hi*lo, lo*hi
                    int ai = (p == 2) ? 1 : 0;
                    int bi2 = (p == 1) ? 1 : 0;
#pragma unroll
                    for (int ks = 0; ks < 4; ks++) {
                        uint32_t en = !(it == 0 && p == 0 && ks == 0);
                        mma_bf16_ss(tmem, dA[ai] + ks * 2, dB[bi2] + ks * 2, MMA_IDESC, en);
                    }
                }
                TCGEN05_COMMIT(sbase + OFF_MBAR + s * 8);
            }
        }
    }
    {
        int sl = (NIT - 1) % 3;
        MBARRIER_WAIT_PARITY(sbase + OFF_MBAR + sl * 8, ph[sl]);
    }
    TCGEN05_FENCE_AFTER();

    {
        int sp = wid & 3;
        int half = wid >> 2;
        uint32_t dr[64];
        TCGEN05_LD_32X32B_X32(dr, tmem + half * 64);
        TCGEN05_LD_32X32B_X32(dr + 32, tmem + half * 64 + 32);
        TCGEN05_WAIT_LD();
        TCGEN05_FENCE_BEFORE();

        int m = m0 + sp * 32 + lid;
        float* obase = (n0g < 256) ? out : (out + (size_t)BATCH * NN * FF);
        int nc0 = (n0g & 255) + half * 64;
        float* orow = obase + (size_t)b * NN * FF + (size_t)m * FF + nc0;
#pragma unroll
        for (int c = 0; c < 64; c += 4) {
            float4 o;
            o.x = elu_f(__uint_as_float(dr[c + 0]));
            o.y = elu_f(__uint_as_float(dr[c + 1]));
            o.z = elu_f(__uint_as_float(dr[c + 2]));
            o.w = elu_f(__uint_as_float(dr[c + 3]));
            *(float4*)(orow + c) = o;
        }
    }

    __syncthreads();
    if (tid == 0) {
        MBARRIER_INVAL(sbase + OFF_MBAR);
        MBARRIER_INVAL(sbase + OFF_MBAR + 8);
        MBARRIER_INVAL(sbase + OFF_MBAR + 16);
    }
    __syncthreads();
    if (wid == 0) {
        TCGEN05_RELINQUISH();
        TCGEN05_DEALLOC(tmem, 128);
    }
#else
    // ---------------- SIMT fallback (compile-only; sm_103a branch runs) -----
    float* As = (float*)smem;                  // [16][128]
    float* Bs = (float*)(smem + 16 * 128 * 4); // [16][128]
    int tx = tid & 15, ty = tid >> 4;
    float acc[8][8] = {};
    for (int k0 = 0; k0 < NN; k0 += 16) {
#pragma unroll
        for (int i = 0; i < 8; i++) {
            int idx = tid + i * 256;           // 0..2047
            int row = idx >> 4, kk = idx & 15;
            As[kk * 128 + row] = __bfloat162float(Ah[(size_t)(m0 + row) * NN + k0 + kk]) +
                                 __bfloat162float(Al[(size_t)(m0 + row) * NN + k0 + kk]);
            Bs[kk * 128 + row] = __bfloat162float(Bh[(size_t)row * NN + k0 + kk]) +
                                 __bfloat162float(Bl[(size_t)row * NN + k0 + kk]);
        }
        __syncthreads();
#pragma unroll
        for (int kk = 0; kk < 16; kk++) {
            float av[8], bv[8];
#pragma unroll
            for (int i = 0; i < 8; i++) av[i] = As[kk * 128 + ty * 8 + i];
#pragma unroll
            for (int j = 0; j < 8; j++) bv[j] = Bs[kk * 128 + tx * 8 + j];
#pragma unroll
            for (int i = 0; i < 8; i++)
#pragma unroll
                for (int j = 0; j < 8; j++) acc[i][j] += av[i] * bv[j];
        }
        __syncthreads();
    }
    float* obase = (n0g < 256) ? out : (out + (size_t)BATCH * NN * FF);
    int nc0 = (n0g & 255);
#pragma unroll
    for (int i = 0; i < 8; i++) {
        int m = m0 + ty * 8 + i;
#pragma unroll
        for (int j = 0; j < 8; j++) {
            int n = nc0 + tx * 8 + j;
            obase[(size_t)b * NN * FF + (size_t)m * FF + n] = elu_f(acc[i][j]);
        }
    }
#endif
}

// ---------------------------------------------------------------------------
extern "C" void kernel_launch(void* const* d_in, const int* in_sizes, int n_in,
                              void* d_out, int out_size) {
    const float* h     = (const float*)d_in[0];
    const int*   adj   = (const int*)  d_in[1];
    const float* lrgt1 = (const float*)d_in[2];
    const float* W1    = (const float*)d_in[3];
    const float* W2    = (const float*)d_in[4];
    const float* a     = (const float*)d_in[5];
    float* out = (float*)d_out;

    __nv_bfloat16 *ath, *atl, *bth, *btl;
    cudaGetSymbolAddress((void**)&ath, d_att_hi);
    cudaGetSymbolAddress((void**)&atl, d_att_lo);
    cudaGetSymbolAddress((void**)&bth, d_bth);
    cudaGetSymbolAddress((void**)&btl, d_btl);
    float* s1;  cudaGetSymbolAddress((void**)&s1,  d_s1);
    float* s2;  cudaGetSymbolAddress((void**)&s2,  d_s2);
    float* v;   cudaGetSymbolAddress((void**)&v,   d_v);

    v_kernel<<<1, 256>>>(W1, a, v);

    {
        dim3 grid(BN / 64, FF / 64, 2);
        feat_gemm<<<grid, 256>>>(h, lrgt1, W1, W2, bth, btl);
    }

    scores_kernel<<<BN, 256>>>(h, v, s1, s2);
    softmax_kernel<<<BN, 256>>>(adj, s1, s2, ath, atl);

    {
        cudaFuncSetAttribute(attn_mma, cudaFuncAttributeMaxDynamicSharedMemorySize, ATTN_SMEM_BYTES);
        dim3 grid(NN / 128, NFEAT / 128, BATCH);
        attn_mma<<<grid, 256, ATTN_SMEM_BYTES>>>(ath, atl, bth, btl, out);
    }
}

// round 7
// speedup vs baseline: 4.6877x; 1.4423x over previous
#include <cuda_runtime.h>
#include <cuda_bf16.h>
#include <cstdint>
#include <math.h>

#define BATCH 8
#define NN 2048
#define FF 256
#define NFEAT 512              // Wh (256) stacked with wl (256)
#define BN (BATCH * NN)        // 16384
#define ALPHA 0.2f

// ---------------- scratch (static device allocations; no cudaMalloc) --------
__device__ __nv_bfloat16 d_att_hi[(size_t)BATCH * NN * NN];  // 67 MB
__device__ __nv_bfloat16 d_att_lo[(size_t)BATCH * NN * NN];  // 67 MB
__device__ __nv_bfloat16 d_bth[(size_t)BATCH * NFEAT * NN];  // 16 MB  [b][feat][node]
__device__ __nv_bfloat16 d_btl[(size_t)BATCH * NFEAT * NN];  // 16 MB
__device__ __nv_bfloat16 d_xh[(size_t)2 * BN * FF];          // h|lr hi
__device__ __nv_bfloat16 d_xl[(size_t)2 * BN * FF];          // h|lr lo
__device__ __nv_bfloat16 d_wth[2 * FF * FF];                 // W1^T|W2^T hi
__device__ __nv_bfloat16 d_wtl[2 * FF * FF];
__device__ float d_s1[BN];
__device__ float d_s2[BN];
__device__ float d_v[2 * FF];

// ---------------- kernel 1: v1 = W1 @ a[:F], v2 = W1 @ a[F:] ----------------
__global__ void v_kernel(const float* __restrict__ W1, const float* __restrict__ a,
                         float* __restrict__ v) {
    int k = threadIdx.x;
    float acc1 = 0.f, acc2 = 0.f;
    const float* wrow = W1 + (size_t)k * FF;
#pragma unroll 8
    for (int c = 0; c < FF; c++) {
        float w = wrow[c];
        acc1 += w * a[c];
        acc2 += w * a[FF + c];
    }
    v[k] = acc1;
    v[FF + k] = acc2;
}

// ------------- split kernels: fp32 -> bf16 hi/lo ----------------------------
__device__ __forceinline__ void split1(float p, __nv_bfloat16& hi, __nv_bfloat16& lo) {
    hi = __float2bfloat16(p);
    lo = __float2bfloat16(p - __bfloat162float(hi));
}

__global__ void split_x(const float* __restrict__ h, const float* __restrict__ lr,
                        __nv_bfloat16* __restrict__ hi, __nv_bfloat16* __restrict__ lo) {
    int z = blockIdx.y;
    const float4* src = (const float4*)(z ? lr : h);
    size_t i4 = (size_t)blockIdx.x * 256 + threadIdx.x;   // BN*FF/4 = 1048576 total
    float4 v = src[i4];
    union { __nv_bfloat16 h[4]; uint2 u; } H, L;
    split1(v.x, H.h[0], L.h[0]);
    split1(v.y, H.h[1], L.h[1]);
    split1(v.z, H.h[2], L.h[2]);
    split1(v.w, H.h[3], L.h[3]);
    size_t o = (size_t)z * BN * FF / 4 + i4;
    ((uint2*)hi)[o] = H.u;
    ((uint2*)lo)[o] = L.u;
}

__global__ void split_w(const float* __restrict__ W1, const float* __restrict__ W2,
                        __nv_bfloat16* __restrict__ wth, __nv_bfloat16* __restrict__ wtl) {
    int z = blockIdx.y;
    int n = blockIdx.x;
    int k = threadIdx.x;
    const float* W = z ? W2 : W1;
    float p = W[(size_t)k * FF + n];     // transpose: Wt[n][k] = W[k][n]
    size_t o = (size_t)z * FF * FF + (size_t)n * FF + k;
    __nv_bfloat16 hi, lo;
    split1(p, hi, lo);
    wth[o] = hi;
    wtl[o] = lo;
}

// ---------------- kernel 3: s1 = h.v1, s2 = h.v2 (exact fp32) ---------------
__global__ void scores_kernel(const float* __restrict__ h, const float* __restrict__ v,
                              float* __restrict__ s1, float* __restrict__ s2) {
    int r = blockIdx.x;
    int tid = threadIdx.x;
    float hv = h[(size_t)r * FF + tid];
    float p1 = hv * v[tid];
    float p2 = hv * v[FF + tid];
    __shared__ float r1[256];
    __shared__ float r2[256];
    r1[tid] = p1; r2[tid] = p2;
    __syncthreads();
    for (int s = 128; s > 0; s >>= 1) {
        if (tid < s) { r1[tid] += r1[tid + s]; r2[tid] += r2[tid + s]; }
        __syncthreads();
    }
    if (tid == 0) { s1[r] = r1[0]; s2[r] = r2[0]; }
}

// --------- kernel 4: masked leaky-relu softmax -> bf16 hi/lo split ----------
__global__ void softmax_kernel(const int* __restrict__ adj, const float* __restrict__ s1,
                               const float* __restrict__ s2,
                               __nv_bfloat16* __restrict__ att_hi,
                               __nv_bfloat16* __restrict__ att_lo) {
    int bi = blockIdx.x;
    int b = bi >> 11;
    const int4* arow = (const int4*)(adj + (size_t)bi * NN);
    const float4* s2b = (const float4*)(s2 + (size_t)b * NN);
    float si = s1[bi];

    __shared__ float x[NN];
    __shared__ float redm[8];
    __shared__ float reds[8];
    int tid = threadIdx.x;
    int lane = tid & 31, warp = tid >> 5;

    float lmax = -3.4e38f;
#pragma unroll
    for (int c = 0; c < 2; c++) {
        int j4 = tid + c * 256;
        int4 av = arow[j4];
        float4 sv = s2b[j4];
        float v0 = si + sv.x; v0 = v0 > 0.f ? v0 : ALPHA * v0; v0 = av.x > 0 ? v0 : -9.0e15f;
        float v1 = si + sv.y; v1 = v1 > 0.f ? v1 : ALPHA * v1; v1 = av.y > 0 ? v1 : -9.0e15f;
        float v2 = si + sv.z; v2 = v2 > 0.f ? v2 : ALPHA * v2; v2 = av.z > 0 ? v2 : -9.0e15f;
        float v3 = si + sv.w; v3 = v3 > 0.f ? v3 : ALPHA * v3; v3 = av.w > 0 ? v3 : -9.0e15f;
        int j = j4 * 4;
        x[j] = v0; x[j + 1] = v1; x[j + 2] = v2; x[j + 3] = v3;
        lmax = fmaxf(fmaxf(fmaxf(lmax, v0), fmaxf(v1, v2)), v3);
    }
#pragma unroll
    for (int o = 16; o; o >>= 1) lmax = fmaxf(lmax, __shfl_xor_sync(0xffffffffu, lmax, o));
    if (lane == 0) redm[warp] = lmax;
    __syncthreads();
    float m = redm[0];
#pragma unroll
    for (int w = 1; w < 8; w++) m = fmaxf(m, redm[w]);

    float lsum = 0.f;
#pragma unroll
    for (int c = 0; c < 2; c++) {
        int j = (tid + c * 256) * 4;
        float e0 = __expf(x[j] - m);
        float e1 = __expf(x[j + 1] - m);
        float e2 = __expf(x[j + 2] - m);
        float e3 = __expf(x[j + 3] - m);
        x[j] = e0; x[j + 1] = e1; x[j + 2] = e2; x[j + 3] = e3;
        lsum += (e0 + e1) + (e2 + e3);
    }
#pragma unroll
    for (int o = 16; o; o >>= 1) lsum += __shfl_xor_sync(0xffffffffu, lsum, o);
    if (lane == 0) reds[warp] = lsum;
    __syncthreads();
    float tot = 0.f;
#pragma unroll
    for (int w = 0; w < 8; w++) tot += reds[w];
    float inv = 1.f / tot;

    uint2* oh = (uint2*)(att_hi + (size_t)bi * NN);
    uint2* ol = (uint2*)(att_lo + (size_t)bi * NN);
#pragma unroll
    for (int c = 0; c < 2; c++) {
        int j4 = tid + c * 256;
        int j = j4 * 4;
        union { __nv_bfloat16 h[4]; uint2 u; } H, L;
#pragma unroll
        for (int q = 0; q < 4; q++) {
            float p = x[j + q] * inv;
            H.h[q] = __float2bfloat16(p);
            L.h[q] = __float2bfloat16(p - __bfloat162float(H.h[q]));
        }
        oh[j4] = H.u;
        ol[j4] = L.u;
    }
}

// ======================= shared helpers =====================================
__device__ __forceinline__ uint32_t smem_u32(const void* p) {
    uint32_t a;
    asm("{ .reg .u64 t; cvta.to.shared.u64 t, %1; cvt.u32.u64 %0, t; }"
        : "=r"(a) : "l"(p));
    return a;
}
__device__ __forceinline__ float elu_f(float v) {
    return v > 0.f ? v : (expf(v) - 1.f);
}

#define OFF_TMEM 0
#define OFF_MBAR 8
#define OFF_BUF  1024
#define STAGE_BYTES 98304              // Ahi 16K | Alo 16K | Bhi 32K | Blo 32K
#define MMA_SMEM_BYTES (OFF_BUF + 2 * STAGE_BYTES)   // 197632

#if defined(__CUDA_ARCH__) && (defined(__CUDA_ARCH_FEAT_SM103_ALL) || defined(__CUDA_ARCH_FEAT_SM100_ALL) || defined(__CUDA_ARCH_FEAT_SM101_ALL))
#define HAS_TCGEN05 1
#else
#define HAS_TCGEN05 0
#endif

#if HAS_TCGEN05
// ================= tcgen05 helpers (sm_103a SASS) ===========================
__device__ __forceinline__ uint32_t elect_one_pred() {
    uint32_t pred;
    asm volatile(
        "{\n\t.reg .pred p;\n\telect.sync _|p, 0xFFFFFFFF;\n\t"
        "selp.b32 %0, 1, 0, p;\n\t}" : "=r"(pred));
    return pred;
}
#define MBARRIER_INIT(addr, cnt) \
    asm volatile("mbarrier.init.shared.b64 [%0], %1;" :: "r"((uint32_t)(addr)), "r"((uint32_t)(cnt)) : "memory")
#define MBARRIER_INVAL(addr) \
    asm volatile("mbarrier.inval.shared.b64 [%0];" :: "r"((uint32_t)(addr)) : "memory")
#define MBARRIER_WAIT_PARITY(mbar_smem_addr, phase_parity) do { \
    uint32_t _mbar = (uint32_t)(mbar_smem_addr); \
    uint32_t _parity = (uint32_t)(phase_parity); \
    uint32_t _done; \
    asm volatile( \
        "{\n\t.reg .pred p;\n\t" \
        "mbarrier.try_wait.parity.acquire.cta.shared::cta.b64 p, [%1], %2;\n\t" \
        "selp.b32 %0, 1, 0, p;\n\t}" \
        : "=r"(_done) : "r"(_mbar), "r"(_parity) : "memory"); \
    if (!_done) { \
        asm volatile( \
            "{\n\t.reg .pred P1;\n\t" \
            "WAIT_LOOP_%=:\n\t" \
            "mbarrier.try_wait.parity.acquire.cta.shared::cta.b64 P1, [%0], %1, 0x989680;\n\t" \
            "@P1 bra.uni WAIT_DONE_%=;\n\t" \
            "bra.uni WAIT_LOOP_%=;\n\t" \
            "WAIT_DONE_%=:\n\t}" \
            :: "r"(_mbar), "r"(_parity) : "memory"); \
    } \
} while (0)
#define TCGEN05_ALLOC(saddr, n) \
    asm volatile("tcgen05.alloc.cta_group::1.sync.aligned.shared::cta.b32 [%0], %1;" \
                 :: "r"((uint32_t)(saddr)), "r"((uint32_t)(n)) : "memory")
#define TCGEN05_DEALLOC(tm, n) \
    asm volatile("tcgen05.dealloc.cta_group::1.sync.aligned.b32 %0, %1;" :: "r"(tm), "r"((uint32_t)(n)))
#define TCGEN05_RELINQUISH() \
    asm volatile("tcgen05.relinquish_alloc_permit.cta_group::1.sync.aligned;")
#define TCGEN05_COMMIT(mbar) \
    asm volatile("tcgen05.commit.cta_group::1.mbarrier::arrive::one.shared::cluster.b64 [%0];" \
                 :: "r"((uint32_t)(mbar)) : "memory")
#define TCGEN05_FENCE_AFTER() asm volatile("tcgen05.fence::after_thread_sync;" ::: "memory")
#define TCGEN05_FENCE_BEFORE() asm volatile("tcgen05.fence::before_thread_sync;" ::: "memory")
#define TCGEN05_WAIT_LD() asm volatile("tcgen05.wait::ld.sync.aligned;" ::: "memory")
#define FENCE_PROXY_ASYNC() asm volatile("fence.proxy.async.shared::cta;" ::: "memory")
#define CP_ASYNC16(dst, src) \
    asm volatile("cp.async.cg.shared.global [%0], [%1], 16;" :: "r"((uint32_t)(dst)), "l"(src) : "memory")
#define CP_COMMIT() asm volatile("cp.async.commit_group;" ::: "memory")
#define CP_WAIT(n)  asm volatile("cp.async.wait_group %0;" :: "n"(n) : "memory")
#define TCGEN05_LD_32X32B_X32(r, tmem_addr) \
    asm volatile( \
        "tcgen05.ld.sync.aligned.32x32b.x32.b32 " \
        "{%0, %1, %2, %3, %4, %5, %6, %7, " \
        " %8, %9, %10, %11, %12, %13, %14, %15, " \
        " %16, %17, %18, %19, %20, %21, %22, %23, " \
        " %24, %25, %26, %27, %28, %29, %30, %31}, [%32];" \
        : "=r"((r)[0]),  "=r"((r)[1]),  "=r"((r)[2]),  "=r"((r)[3]), \
          "=r"((r)[4]),  "=r"((r)[5]),  "=r"((r)[6]),  "=r"((r)[7]), \
          "=r"((r)[8]),  "=r"((r)[9]),  "=r"((r)[10]), "=r"((r)[11]), \
          "=r"((r)[12]), "=r"((r)[13]), "=r"((r)[14]), "=r"((r)[15]), \
          "=r"((r)[16]), "=r"((r)[17]), "=r"((r)[18]), "=r"((r)[19]), \
          "=r"((r)[20]), "=r"((r)[21]), "=r"((r)[22]), "=r"((r)[23]), \
          "=r"((r)[24]), "=r"((r)[25]), "=r"((r)[26]), "=r"((r)[27]), \
          "=r"((r)[28]), "=r"((r)[29]), "=r"((r)[30]), "=r"((r)[31]) \
        : "r"(tmem_addr))

static constexpr uint64_t SMEM_DESC_BASE_SW128 =
    (uint64_t(2) << 61) | (uint64_t(1) << 46) | (uint64_t(64) << 32) | (uint64_t(1) << 16);
#define MAKE_SMEM_DESC(base_addr) \
    (SMEM_DESC_BASE_SW128 | ((uint64_t)((base_addr) >> 4) & 0x3FFF))
#define SMEM_SWZ(o) ((o) ^ (((o) >> 3) & 0x70))

__device__ __forceinline__ void mma_bf16_ss(uint32_t d_tmem, uint64_t a_desc,
                                            uint64_t b_desc, uint32_t idesc, uint32_t en) {
    asm volatile(
        "{\n\t.reg .pred p;\n\tsetp.ne.u32 p, %4, 0;\n\t"
        "tcgen05.mma.cta_group::1.kind::f16 [%0], %1, %2, %3, {%5, %5, %5, %5}, p;\n\t}"
        :: "r"(d_tmem), "l"(a_desc), "l"(b_desc), "r"(idesc), "r"(en), "r"(0u)
        : "memory");
}
// idesc: f32 accum, bf16 a/b, N=256, M=128
static constexpr uint32_t MMA_IDESC =
    (1u << 4) | (1u << 7) | (1u << 10) | ((256u / 8) << 17) | ((128u / 16) << 24);
#endif  // HAS_TCGEN05

// ============ kernel 2: feat_mma: BT[hi/lo] = split((x @ W)^T) ==============
// M=128 nodes, N=256 out-features, K=256; tcgen05 bf16x3, 2-stage pipeline.
__global__ void __launch_bounds__(256, 1)
feat_mma(const __nv_bfloat16* __restrict__ xh, const __nv_bfloat16* __restrict__ xl,
         const __nv_bfloat16* __restrict__ wth, const __nv_bfloat16* __restrict__ wtl,
         __nv_bfloat16* __restrict__ BTh, __nv_bfloat16* __restrict__ BTl) {
    extern __shared__ char smem[];
    const int tid = threadIdx.x;
    const int wid = tid >> 5;
    const int lid = tid & 31;
    const int m0 = blockIdx.x * 128;
    const int z = blockIdx.y;
    const __nv_bfloat16* Ah = xh + (size_t)z * BN * FF + (size_t)m0 * FF;
    const __nv_bfloat16* Al = xl + (size_t)z * BN * FF + (size_t)m0 * FF;
    const __nv_bfloat16* Bh = wth + (size_t)z * FF * FF;
    const __nv_bfloat16* Bl = wtl + (size_t)z * FF * FF;
    const int b = m0 >> 11;
    const int node0 = m0 & (NN - 1);

#if HAS_TCGEN05
    uint32_t sbase = smem_u32(smem);
    if (wid == 0) TCGEN05_ALLOC(sbase + OFF_TMEM, 256);
    if (tid == 0) {
        MBARRIER_INIT(sbase + OFF_MBAR, 1);
        MBARRIER_INIT(sbase + OFF_MBAR + 8, 1);
    }
    __syncthreads();
    uint32_t tmem;
    asm volatile("ld.shared.b32 %0, [%1];" : "=r"(tmem) : "r"(sbase + OFF_TMEM));

    auto issue_loads = [&](int it) {
        int s = it & 1;
        int k0 = it * 64;
        uint32_t sb = sbase + OFF_BUF + s * STAGE_BYTES;
#pragma unroll
        for (int i = 0; i < 4; i++) {            // A: 128 rows x 8 chunks
            int idx = tid + i * 256;
            int row = idx >> 3;
            int kc = (idx & 7) * 8;
            uint32_t doff = SMEM_SWZ((uint32_t)(row * 128 + kc * 2));
            CP_ASYNC16(sb + doff,         Ah + (size_t)row * FF + k0 + kc);
            CP_ASYNC16(sb + 16384 + doff, Al + (size_t)row * FF + k0 + kc);
        }
#pragma unroll
        for (int i = 0; i < 8; i++) {            // B: 256 rows x 8 chunks
            int idx = tid + i * 256;
            int row = idx >> 3;
            int kc = (idx & 7) * 8;
            uint32_t doff = SMEM_SWZ((uint32_t)(row * 128 + kc * 2));
            CP_ASYNC16(sb + 32768 + doff, Bh + (size_t)row * FF + k0 + kc);
            CP_ASYNC16(sb + 65536 + doff, Bl + (size_t)row * FF + k0 + kc);
        }
    };

    const int NIT = 4;                           // K = 256
    issue_loads(0); CP_COMMIT();
    issue_loads(1); CP_COMMIT();

    int ph[2] = {0, 0};
    for (int it = 0; it < NIT; it++) {
        int s = it & 1;
        if (it + 1 < NIT) { CP_WAIT(1); } else { CP_WAIT(0); }
        __syncthreads();
        if (wid == 0) {
            FENCE_PROXY_ASYNC();
            if (elect_one_pred()) {
                uint32_t sb = sbase + OFF_BUF + s * STAGE_BYTES;
                uint64_t dA[2] = { MAKE_SMEM_DESC(sb),         MAKE_SMEM_DESC(sb + 16384) };
                uint64_t dB[2] = { MAKE_SMEM_DESC(sb + 32768), MAKE_SMEM_DESC(sb + 65536) };
#pragma unroll
                for (int p = 0; p < 3; p++) {     // hi*hi, hi*lo, lo*hi
                    int ai = (p == 2) ? 1 : 0;
                    int bi2 = (p == 1) ? 1 : 0;
#pragma unroll
                    for (int ks = 0; ks < 4; ks++) {
                        uint32_t en = !(it == 0 && p == 0 && ks == 0);
                        mma_bf16_ss(tmem, dA[ai] + ks * 2, dB[bi2] + ks * 2, MMA_IDESC, en);
                    }
                }
                TCGEN05_COMMIT(sbase + OFF_MBAR + s * 8);
            }
        }
        MBARRIER_WAIT_PARITY(sbase + OFF_MBAR + s * 8, ph[s]);
        ph[s] ^= 1;
        if (it + 2 < NIT) { issue_loads(it + 2); CP_COMMIT(); }
    }
    TCGEN05_FENCE_AFTER();

    // ---- epilogue: TMEM -> smem Ct[node][261] -> transposed bf16 hi/lo ----
    float* Ct = (float*)(smem + OFF_BUF);
    {
        int sp = wid & 3;
        int half = wid >> 2;
        int node = sp * 32 + lid;
#pragma unroll
        for (int c2 = 0; c2 < 4; c2++) {
            uint32_t dr[32];
            TCGEN05_LD_32X32B_X32(dr, tmem + half * 128 + c2 * 32);
            TCGEN05_WAIT_LD();
            int f0 = half * 128 + c2 * 32;
#pragma unroll
            for (int c = 0; c < 32; c++)
                Ct[node * 261 + f0 + c] = __uint_as_float(dr[c]);
        }
        TCGEN05_FENCE_BEFORE();
    }
    __syncthreads();
    {
        int f = tid;     // one out-feature per thread
        __nv_bfloat16* dh = BTh + ((size_t)b * NFEAT + z * 256 + f) * NN + node0;
        __nv_bfloat16* dl = BTl + ((size_t)b * NFEAT + z * 256 + f) * NN + node0;
#pragma unroll 4
        for (int nd = 0; nd < 128; nd += 4) {
            union { __nv_bfloat16 h[4]; uint2 u; } H, L;
#pragma unroll
            for (int q = 0; q < 4; q++) {
                float p = Ct[(nd + q) * 261 + f];
                H.h[q] = __float2bfloat16(p);
                L.h[q] = __float2bfloat16(p - __bfloat162float(H.h[q]));
            }
            *(uint2*)(dh + nd) = H.u;
            *(uint2*)(dl + nd) = L.u;
        }
    }
    __syncthreads();
    if (tid == 0) { MBARRIER_INVAL(sbase + OFF_MBAR); MBARRIER_INVAL(sbase + OFF_MBAR + 8); }
    __syncthreads();
    if (wid == 0) {
        TCGEN05_RELINQUISH();
        TCGEN05_DEALLOC(tmem, 256);
    }
#else
    // correct (slow) fallback — never runs when sm_103a SASS is present
    for (int e = tid; e < 128 * 256; e += 256) {
        int mi = e >> 8, nj = e & 255;
        float acc = 0.f;
        for (int k = 0; k < FF; k++) {
            float av = __bfloat162float(Ah[(size_t)mi * FF + k]) +
                       __bfloat162float(Al[(size_t)mi * FF + k]);
            float bv = __bfloat162float(Bh[(size_t)nj * FF + k]) +
                       __bfloat162float(Bl[(size_t)nj * FF + k]);
            acc += av * bv;
        }
        __nv_bfloat16 hi, lo;
        split1(acc, hi, lo);
        size_t o = ((size_t)b * NFEAT + z * 256 + nj) * NN + node0 + mi;
        BTh[o] = hi;
        BTl[o] = lo;
    }
#endif
}

// ============== kernel 5: attn_mma: out = elu(att @ [Wh|wl]) ================
// M=128, N=256 per CTA; K=2048 in 32 tiles of 64; 2-stage x 96KB pipeline.
__global__ void __launch_bounds__(256, 1)
attn_mma(const __nv_bfloat16* __restrict__ att_hi, const __nv_bfloat16* __restrict__ att_lo,
         const __nv_bfloat16* __restrict__ BTh, const __nv_bfloat16* __restrict__ BTl,
         float* __restrict__ out) {
    extern __shared__ char smem[];
    const int tid = threadIdx.x;
    const int wid = tid >> 5;
    const int lid = tid & 31;
    const int b = blockIdx.z;
    const int m0 = blockIdx.x * 128;
    const int n0g = blockIdx.y * 256;     // 0 -> out1, 256 -> out2
    const __nv_bfloat16* Ah = att_hi + (size_t)b * NN * NN;
    const __nv_bfloat16* Al = att_lo + (size_t)b * NN * NN;
    const __nv_bfloat16* Bh = BTh + (size_t)b * NFEAT * NN + (size_t)n0g * NN;
    const __nv_bfloat16* Bl = BTl + (size_t)b * NFEAT * NN + (size_t)n0g * NN;

#if HAS_TCGEN05
    uint32_t sbase = smem_u32(smem);
    if (wid == 0) TCGEN05_ALLOC(sbase + OFF_TMEM, 256);
    if (tid == 0) {
        MBARRIER_INIT(sbase + OFF_MBAR, 1);
        MBARRIER_INIT(sbase + OFF_MBAR + 8, 1);
    }
    __syncthreads();
    uint32_t tmem;
    asm volatile("ld.shared.b32 %0, [%1];" : "=r"(tmem) : "r"(sbase + OFF_TMEM));

    auto issue_loads = [&](int it) {
        int s = it & 1;
        int k0 = it * 64;
        uint32_t sb = sbase + OFF_BUF + s * STAGE_BYTES;
#pragma unroll
        for (int i = 0; i < 4; i++) {            // A: 128 rows x 8 chunks
            int idx = tid + i * 256;
            int row = idx >> 3;
            int kc = (idx & 7) * 8;
            uint32_t doff = SMEM_SWZ((uint32_t)(row * 128 + kc * 2));
            CP_ASYNC16(sb + doff,         Ah + (size_t)(m0 + row) * NN + k0 + kc);
            CP_ASYNC16(sb + 16384 + doff, Al + (size_t)(m0 + row) * NN + k0 + kc);
        }
#pragma unroll
        for (int i = 0; i < 8; i++) {            // B: 256 rows x 8 chunks
            int idx = tid + i * 256;
            int row = idx >> 3;
            int kc = (idx & 7) * 8;
            uint32_t doff = SMEM_SWZ((uint32_t)(row * 128 + kc * 2));
            CP_ASYNC16(sb + 32768 + doff, Bh + (size_t)row * NN + k0 + kc);
            CP_ASYNC16(sb + 65536 + doff, Bl + (size_t)row * NN + k0 + kc);
        }
    };

    const int NIT = NN / 64;   // 32
    issue_loads(0); CP_COMMIT();
    issue_loads(1); CP_COMMIT();

    int ph[2] = {0, 0};
    for (int it = 0; it < NIT; it++) {
        int s = it & 1;
        if (it + 1 < NIT) { CP_WAIT(1); } else { CP_WAIT(0); }
        __syncthreads();
        if (wid == 0) {
            FENCE_PROXY_ASYNC();
            if (elect_one_pred()) {
                uint32_t sb = sbase + OFF_BUF + s * STAGE_BYTES;
                uint64_t dA[2] = { MAKE_SMEM_DESC(sb),         MAKE_SMEM_DESC(sb + 16384) };
                uint64_t dB[2] = { MAKE_SMEM_DESC(sb + 32768), MAKE_SMEM_DESC(sb + 65536) };
#pragma unroll
                for (int p = 0; p < 3; p++) {     // hi*hi, hi*lo, lo*hi
                    int ai = (p == 2) ? 1 : 0;
                    int bi2 = (p == 1) ? 1 : 0;
#pragma unroll
                    for (int ks = 0; ks < 4; ks++) {
                        uint32_t en = !(it == 0 && p == 0 && ks == 0);
                        mma_bf16_ss(tmem, dA[ai] + ks * 2, dB[bi2] + ks * 2, MMA_IDESC, en);
                    }
                }
                TCGEN05_COMMIT(sbase + OFF_MBAR + s * 8);
            }
        }
        MBARRIER_WAIT_PARITY(sbase + OFF_MBAR + s * 8, ph[s]);
        ph[s] ^= 1;
        if (it + 2 < NIT) { issue_loads(it + 2); CP_COMMIT(); }
    }
    TCGEN05_FENCE_AFTER();

    // ---- epilogue: 256 cols, warp = (subpartition, col-half), ELU + store --
    {
        int sp = wid & 3;
        int half = wid >> 2;
        int m = m0 + sp * 32 + lid;
        float* orow = out + (size_t)(n0g >> 8) * BATCH * NN * FF
                          + (size_t)b * NN * FF + (size_t)m * FF;
#pragma unroll
        for (int c2 = 0; c2 < 4; c2++) {
            uint32_t dr[32];
            TCGEN05_LD_32X32B_X32(dr, tmem + half * 128 + c2 * 32);
            TCGEN05_WAIT_LD();
            int nc = half * 128 + c2 * 32;
#pragma unroll
            for (int c = 0; c < 32; c += 4) {
                float4 o;
                o.x = elu_f(__uint_as_float(dr[c + 0]));
                o.y = elu_f(__uint_as_float(dr[c + 1]));
                o.z = elu_f(__uint_as_float(dr[c + 2]));
                o.w = elu_f(__uint_as_float(dr[c + 3]));
                *(float4*)(orow + nc + c) = o;
            }
        }
        TCGEN05_FENCE_BEFORE();
    }

    __syncthreads();
    if (tid == 0) { MBARRIER_INVAL(sbase + OFF_MBAR); MBARRIER_INVAL(sbase + OFF_MBAR + 8); }
    __syncthreads();
    if (wid == 0) {
        TCGEN05_RELINQUISH();
        TCGEN05_DEALLOC(tmem, 256);
    }
#else
    // correct (slow) fallback — never runs when sm_103a SASS is present
    for (int e = tid; e < 128 * 256; e += 256) {
        int mi = e >> 8, nj = e & 255;
        float acc = 0.f;
        for (int k = 0; k < NN; k++) {
            float av = __bfloat162float(Ah[(size_t)(m0 + mi) * NN + k]) +
                       __bfloat162float(Al[(size_t)(m0 + mi) * NN + k]);
            float bv = __bfloat162float(Bh[(size_t)nj * NN + k]) +
                       __bfloat162float(Bl[(size_t)nj * NN + k]);
            acc += av * bv;
        }
        out[(size_t)(n0g >> 8) * BATCH * NN * FF + (size_t)b * NN * FF
            + (size_t)(m0 + mi) * FF + nj] = elu_f(acc);
    }
#endif
}

// ---------------------------------------------------------------------------
extern "C" void kernel_launch(void* const* d_in, const int* in_sizes, int n_in,
                              void* d_out, int out_size) {
    const float* h     = (const float*)d_in[0];
    const int*   adj   = (const int*)  d_in[1];
    const float* lrgt1 = (const float*)d_in[2];
    const float* W1    = (const float*)d_in[3];
    const float* W2    = (const float*)d_in[4];
    const float* a     = (const float*)d_in[5];
    float* out = (float*)d_out;

    __nv_bfloat16 *ath, *atl, *bth, *btl, *xh, *xl, *wth, *wtl;
    cudaGetSymbolAddress((void**)&ath, d_att_hi);
    cudaGetSymbolAddress((void**)&atl, d_att_lo);
    cudaGetSymbolAddress((void**)&bth, d_bth);
    cudaGetSymbolAddress((void**)&btl, d_btl);
    cudaGetSymbolAddress((void**)&xh,  d_xh);
    cudaGetSymbolAddress((void**)&xl,  d_xl);
    cudaGetSymbolAddress((void**)&wth, d_wth);
    cudaGetSymbolAddress((void**)&wtl, d_wtl);
    float* s1;  cudaGetSymbolAddress((void**)&s1,  d_s1);
    float* s2;  cudaGetSymbolAddress((void**)&s2,  d_s2);
    float* v;   cudaGetSymbolAddress((void**)&v,   d_v);

    v_kernel<<<1, 256>>>(W1, a, v);
    split_x<<<dim3(BN * FF / 1024, 2), 256>>>(h, lrgt1, xh, xl);
    split_w<<<dim3(FF, 2), 256>>>(W1, W2, wth, wtl);

    cudaFuncSetAttribute(feat_mma, cudaFuncAttributeMaxDynamicSharedMemorySize, MMA_SMEM_BYTES);
    feat_mma<<<dim3(BN / 128, 2), 256, MMA_SMEM_BYTES>>>(xh, xl, wth, wtl, bth, btl);

    scores_kernel<<<BN, 256>>>(h, v, s1, s2);
    softmax_kernel<<<BN, 256>>>(adj, s1, s2, ath, atl);

    cudaFuncSetAttribute(attn_mma, cudaFuncAttributeMaxDynamicSharedMemorySize, MMA_SMEM_BYTES);
    attn_mma<<<dim3(NN / 128, 2, BATCH), 256, MMA_SMEM_BYTES>>>(ath, atl, bth, btl, out);
}

// round 12
// speedup vs baseline: 5.4576x; 1.1643x over previous
#include <cuda_runtime.h>
#include <cuda_bf16.h>
#include <cstdint>
#include <math.h>

#define BATCH 8
#define NN 2048
#define FF 256
#define NFEAT 512              // Wh (256) stacked with wl (256)
#define BN (BATCH * NN)        // 16384
#define ALPHA 0.2f

// ---------------- scratch (static device allocations; no cudaMalloc) --------
__device__ __nv_bfloat16 d_att_hi[(size_t)BATCH * NN * NN];  // 67 MB
__device__ __nv_bfloat16 d_att_lo[(size_t)BATCH * NN * NN];  // 67 MB
__device__ __nv_bfloat16 d_bth[(size_t)BATCH * NFEAT * NN];  // 16 MB  [b][feat][node]
__device__ __nv_bfloat16 d_btl[(size_t)BATCH * NFEAT * NN];  // 16 MB
__device__ __nv_bfloat16 d_xh[(size_t)2 * BN * FF];          // h|lr hi
__device__ __nv_bfloat16 d_xl[(size_t)2 * BN * FF];          // h|lr lo
__device__ __nv_bfloat16 d_wth[2 * FF * FF];                 // W1^T|W2^T hi
__device__ __nv_bfloat16 d_wtl[2 * FF * FF];
__device__ float d_s1[BN];
__device__ float d_s2[BN];
__device__ float d_v[2 * FF];

// ---------------- kernel 1: v1 = W1 @ a[:F], v2 = W1 @ a[F:] ----------------
__global__ void v_kernel(const float* __restrict__ W1, const float* __restrict__ a,
                         float* __restrict__ v) {
    int k = threadIdx.x;
    float acc1 = 0.f, acc2 = 0.f;
    const float* wrow = W1 + (size_t)k * FF;
#pragma unroll 8
    for (int c = 0; c < FF; c++) {
        float w = wrow[c];
        acc1 += w * a[c];
        acc2 += w * a[FF + c];
    }
    v[k] = acc1;
    v[FF + k] = acc2;
}

// ------------- split kernels: fp32 -> bf16 hi/lo ----------------------------
__device__ __forceinline__ void split1(float p, __nv_bfloat16& hi, __nv_bfloat16& lo) {
    hi = __float2bfloat16(p);
    lo = __float2bfloat16(p - __bfloat162float(hi));
}

__global__ void split_x(const float* __restrict__ h, const float* __restrict__ lr,
                        __nv_bfloat16* __restrict__ hi, __nv_bfloat16* __restrict__ lo) {
    int z = blockIdx.y;
    const float4* src = (const float4*)(z ? lr : h);
    size_t i4 = (size_t)blockIdx.x * 256 + threadIdx.x;
    float4 v = src[i4];
    union { __nv_bfloat16 h[4]; uint2 u; } H, L;
    split1(v.x, H.h[0], L.h[0]);
    split1(v.y, H.h[1], L.h[1]);
    split1(v.z, H.h[2], L.h[2]);
    split1(v.w, H.h[3], L.h[3]);
    size_t o = (size_t)z * BN * FF / 4 + i4;
    ((uint2*)hi)[o] = H.u;
    ((uint2*)lo)[o] = L.u;
}

__global__ void split_w(const float* __restrict__ W1, const float* __restrict__ W2,
                        __nv_bfloat16* __restrict__ wth, __nv_bfloat16* __restrict__ wtl) {
    int z = blockIdx.y;
    int n = blockIdx.x;
    int k = threadIdx.x;
    const float* W = z ? W2 : W1;
    float p = W[(size_t)k * FF + n];     // transpose: Wt[n][k] = W[k][n]
    size_t o = (size_t)z * FF * FF + (size_t)n * FF + k;
    __nv_bfloat16 hi, lo;
    split1(p, hi, lo);
    wth[o] = hi;
    wtl[o] = lo;
}

// ---------------- kernel 3: s1 = h.v1, s2 = h.v2 (exact fp32) ---------------
__global__ void scores_kernel(const float* __restrict__ h, const float* __restrict__ v,
                              float* __restrict__ s1, float* __restrict__ s2) {
    int r = blockIdx.x;
    int tid = threadIdx.x;
    float hv = h[(size_t)r * FF + tid];
    float p1 = hv * v[tid];
    float p2 = hv * v[FF + tid];
    __shared__ float r1[256];
    __shared__ float r2[256];
    r1[tid] = p1; r2[tid] = p2;
    __syncthreads();
    for (int s = 128; s > 0; s >>= 1) {
        if (tid < s) { r1[tid] += r1[tid + s]; r2[tid] += r2[tid + s]; }
        __syncthreads();
    }
    if (tid == 0) { s1[r] = r1[0]; s2[r] = r2[0]; }
}

// --------- kernel 4: masked leaky-relu softmax -> bf16 hi/lo split ----------
__global__ void softmax_kernel(const int* __restrict__ adj, const float* __restrict__ s1,
                               const float* __restrict__ s2,
                               __nv_bfloat16* __restrict__ att_hi,
                               __nv_bfloat16* __restrict__ att_lo) {
    int bi = blockIdx.x;
    int b = bi >> 11;
    const int4* arow = (const int4*)(adj + (size_t)bi * NN);
    const float4* s2b = (const float4*)(s2 + (size_t)b * NN);
    float si = s1[bi];

    __shared__ float x[NN];
    __shared__ float redm[8];
    __shared__ float reds[8];
    int tid = threadIdx.x;
    int lane = tid & 31, warp = tid >> 5;

    float lmax = -3.4e38f;
#pragma unroll
    for (int c = 0; c < 2; c++) {
        int j4 = tid + c * 256;
        int4 av = arow[j4];
        float4 sv = s2b[j4];
        float v0 = si + sv.x; v0 = v0 > 0.f ? v0 : ALPHA * v0; v0 = av.x > 0 ? v0 : -9.0e15f;
        float v1 = si + sv.y; v1 = v1 > 0.f ? v1 : ALPHA * v1; v1 = av.y > 0 ? v1 : -9.0e15f;
        float v2 = si + sv.z; v2 = v2 > 0.f ? v2 : ALPHA * v2; v2 = av.z > 0 ? v2 : -9.0e15f;
        float v3 = si + sv.w; v3 = v3 > 0.f ? v3 : ALPHA * v3; v3 = av.w > 0 ? v3 : -9.0e15f;
        int j = j4 * 4;
        x[j] = v0; x[j + 1] = v1; x[j + 2] = v2; x[j + 3] = v3;
        lmax = fmaxf(fmaxf(fmaxf(lmax, v0), fmaxf(v1, v2)), v3);
    }
#pragma unroll
    for (int o = 16; o; o >>= 1) lmax = fmaxf(lmax, __shfl_xor_sync(0xffffffffu, lmax, o));
    if (lane == 0) redm[warp] = lmax;
    __syncthreads();
    float m = redm[0];
#pragma unroll
    for (int w = 1; w < 8; w++) m = fmaxf(m, redm[w]);

    float lsum = 0.f;
#pragma unroll
    for (int c = 0; c < 2; c++) {
        int j = (tid + c * 256) * 4;
        float e0 = __expf(x[j] - m);
        float e1 = __expf(x[j + 1] - m);
        float e2 = __expf(x[j + 2] - m);
        float e3 = __expf(x[j + 3] - m);
        x[j] = e0; x[j + 1] = e1; x[j + 2] = e2; x[j + 3] = e3;
        lsum += (e0 + e1) + (e2 + e3);
    }
#pragma unroll
    for (int o = 16; o; o >>= 1) lsum += __shfl_xor_sync(0xffffffffu, lsum, o);
    if (lane == 0) reds[warp] = lsum;
    __syncthreads();
    float tot = 0.f;
#pragma unroll
    for (int w = 0; w < 8; w++) tot += reds[w];
    float inv = 1.f / tot;

    uint2* oh = (uint2*)(att_hi + (size_t)bi * NN);
    uint2* ol = (uint2*)(att_lo + (size_t)bi * NN);
#pragma unroll
    for (int c = 0; c < 2; c++) {
        int j4 = tid + c * 256;
        int j = j4 * 4;
        union { __nv_bfloat16 h[4]; uint2 u; } H, L;
#pragma unroll
        for (int q = 0; q < 4; q++) {
            float p = x[j + q] * inv;
            H.h[q] = __float2bfloat16(p);
            L.h[q] = __float2bfloat16(p - __bfloat162float(H.h[q]));
        }
        oh[j4] = H.u;
        ol[j4] = L.u;
    }
}

// ======================= shared helpers =====================================
__device__ __forceinline__ uint32_t smem_u32(const void* p) {
    uint32_t a;
    asm("{ .reg .u64 t; cvta.to.shared.u64 t, %1; cvt.u32.u64 %0, t; }"
        : "=r"(a) : "l"(p));
    return a;
}
__device__ __forceinline__ float elu_f(float v) {
    return v > 0.f ? v : (__expf(v) - 1.f);
}

#define OFF_TMEM 0
#define OFF_MBAR 8
#define OFF_BUF  1024
#define STAGE_BYTES 49152              // Ahi 8K | Alo 8K | Bhi 16K | Blo 16K  (K-tile 32, SW64)
#define NSTAGE 4
#define MMA_SMEM_BYTES (OFF_BUF + NSTAGE * STAGE_BYTES)   // 197632
#define CT_PAD 264                     // floats; 264*4=1056 bytes, 16B-aligned rows

#if defined(__CUDA_ARCH__) && (defined(__CUDA_ARCH_FEAT_SM103_ALL) || defined(__CUDA_ARCH_FEAT_SM100_ALL) || defined(__CUDA_ARCH_FEAT_SM101_ALL))
#define HAS_TCGEN05 1
#else
#define HAS_TCGEN05 0
#endif

#if HAS_TCGEN05
// ================= tcgen05 helpers (sm_103a SASS) ===========================
__device__ __forceinline__ uint32_t elect_one_pred() {
    uint32_t pred;
    asm volatile(
        "{\n\t.reg .pred p;\n\telect.sync _|p, 0xFFFFFFFF;\n\t"
        "selp.b32 %0, 1, 0, p;\n\t}" : "=r"(pred));
    return pred;
}
#define MBARRIER_INIT(addr, cnt) \
    asm volatile("mbarrier.init.shared.b64 [%0], %1;" :: "r"((uint32_t)(addr)), "r"((uint32_t)(cnt)) : "memory")
#define MBARRIER_INVAL(addr) \
    asm volatile("mbarrier.inval.shared.b64 [%0];" :: "r"((uint32_t)(addr)) : "memory")
#define MBARRIER_WAIT_PARITY(mbar_smem_addr, phase_parity) do { \
    uint32_t _mbar = (uint32_t)(mbar_smem_addr); \
    uint32_t _parity = (uint32_t)(phase_parity); \
    uint32_t _done; \
    asm volatile( \
        "{\n\t.reg .pred p;\n\t" \
        "mbarrier.try_wait.parity.acquire.cta.shared::cta.b64 p, [%1], %2;\n\t" \
        "selp.b32 %0, 1, 0, p;\n\t}" \
        : "=r"(_done) : "r"(_mbar), "r"(_parity) : "memory"); \
    if (!_done) { \
        asm volatile( \
            "{\n\t.reg .pred P1;\n\t" \
            "WAIT_LOOP_%=:\n\t" \
            "mbarrier.try_wait.parity.acquire.cta.shared::cta.b64 P1, [%0], %1, 0x989680;\n\t" \
            "@P1 bra.uni WAIT_DONE_%=;\n\t" \
            "bra.uni WAIT_LOOP_%=;\n\t" \
            "WAIT_DONE_%=:\n\t}" \
            :: "r"(_mbar), "r"(_parity) : "memory"); \
    } \
} while (0)
#define TCGEN05_ALLOC(saddr, n) \
    asm volatile("tcgen05.alloc.cta_group::1.sync.aligned.shared::cta.b32 [%0], %1;" \
                 :: "r"((uint32_t)(saddr)), "r"((uint32_t)(n)) : "memory")
#define TCGEN05_DEALLOC(tm, n) \
    asm volatile("tcgen05.dealloc.cta_group::1.sync.aligned.b32 %0, %1;" :: "r"(tm), "r"((uint32_t)(n)))
#define TCGEN05_RELINQUISH() \
    asm volatile("tcgen05.relinquish_alloc_permit.cta_group::1.sync.aligned;")
#define TCGEN05_COMMIT(mbar) \
    asm volatile("tcgen05.commit.cta_group::1.mbarrier::arrive::one.shared::cluster.b64 [%0];" \
                 :: "r"((uint32_t)(mbar)) : "memory")
#define TCGEN05_FENCE_AFTER() asm volatile("tcgen05.fence::after_thread_sync;" ::: "memory")
#define TCGEN05_FENCE_BEFORE() asm volatile("tcgen05.fence::before_thread_sync;" ::: "memory")
#define TCGEN05_WAIT_LD() asm volatile("tcgen05.wait::ld.sync.aligned;" ::: "memory")
#define FENCE_PROXY_ASYNC() asm volatile("fence.proxy.async.shared::cta;" ::: "memory")
#define CP_ASYNC16(dst, src) \
    asm volatile("cp.async.cg.shared.global [%0], [%1], 16;" :: "r"((uint32_t)(dst)), "l"(src) : "memory")
#define CP_COMMIT() asm volatile("cp.async.commit_group;" ::: "memory")
#define CP_WAIT(n)  asm volatile("cp.async.wait_group %0;" :: "n"(n) : "memory")
#define TCGEN05_LD_32X32B_X32(r, tmem_addr) \
    asm volatile( \
        "tcgen05.ld.sync.aligned.32x32b.x32.b32 " \
        "{%0, %1, %2, %3, %4, %5, %6, %7, " \
        " %8, %9, %10, %11, %12, %13, %14, %15, " \
        " %16, %17, %18, %19, %20, %21, %22, %23, " \
        " %24, %25, %26, %27, %28, %29, %30, %31}, [%32];" \
        : "=r"((r)[0]),  "=r"((r)[1]),  "=r"((r)[2]),  "=r"((r)[3]), \
          "=r"((r)[4]),  "=r"((r)[5]),  "=r"((r)[6]),  "=r"((r)[7]), \
          "=r"((r)[8]),  "=r"((r)[9]),  "=r"((r)[10]), "=r"((r)[11]), \
          "=r"((r)[12]), "=r"((r)[13]), "=r"((r)[14]), "=r"((r)[15]), \
          "=r"((r)[16]), "=r"((r)[17]), "=r"((r)[18]), "=r"((r)[19]), \
          "=r"((r)[20]), "=r"((r)[21]), "=r"((r)[22]), "=r"((r)[23]), \
          "=r"((r)[24]), "=r"((r)[25]), "=r"((r)[26]), "=r"((r)[27]), \
          "=r"((r)[28]), "=r"((r)[29]), "=r"((r)[30]), "=r"((r)[31]) \
        : "r"(tmem_addr))

// SW64 K-major descriptor: layout=4, version=1, SBO=32 (512B = 8 rows x 64B), LBO=1
static constexpr uint64_t SMEM_DESC_BASE_SW64 =
    (uint64_t(4) << 61) | (uint64_t(1) << 46) | (uint64_t(32) << 32) | (uint64_t(1) << 16);
#define MAKE_DESC64(base_addr) \
    (SMEM_DESC_BASE_SW64 | ((uint64_t)((base_addr) >> 4) & 0x3FFF))
#define SMEM_SWZ64(o) ((o) ^ (((o) >> 3) & 0x30))

__device__ __forceinline__ void mma_bf16_ss(uint32_t d_tmem, uint64_t a_desc,
                                            uint64_t b_desc, uint32_t idesc, uint32_t en) {
    asm volatile(
        "{\n\t.reg .pred p;\n\tsetp.ne.u32 p, %4, 0;\n\t"
        "tcgen05.mma.cta_group::1.kind::f16 [%0], %1, %2, %3, {%5, %5, %5, %5}, p;\n\t}"
        :: "r"(d_tmem), "l"(a_desc), "l"(b_desc), "r"(idesc), "r"(en), "r"(0u)
        : "memory");
}
// idesc: f32 accum, bf16 a/b, N=256, M=128
static constexpr uint32_t MMA_IDESC =
    (1u << 4) | (1u << 7) | (1u << 10) | ((256u / 8) << 17) | ((128u / 16) << 24);
#endif  // HAS_TCGEN05

// ============ kernel 2: feat_mma: BT[hi/lo] = split((x @ W)^T) ==============
// M=128 nodes, N=256 out-features, K=256; 4-stage K32 pipeline, SW64.
__global__ void __launch_bounds__(256, 1)
feat_mma(const __nv_bfloat16* __restrict__ xh, const __nv_bfloat16* __restrict__ xl,
         const __nv_bfloat16* __restrict__ wth, const __nv_bfloat16* __restrict__ wtl,
         __nv_bfloat16* __restrict__ BTh, __nv_bfloat16* __restrict__ BTl) {
    extern __shared__ char smem[];
    const int tid = threadIdx.x;
    const int wid = tid >> 5;
    const int lid = tid & 31;
    const int m0 = blockIdx.x * 128;
    const int z = blockIdx.y;
    const __nv_bfloat16* Ah = xh + (size_t)z * BN * FF + (size_t)m0 * FF;
    const __nv_bfloat16* Al = xl + (size_t)z * BN * FF + (size_t)m0 * FF;
    const __nv_bfloat16* Bh = wth + (size_t)z * FF * FF;
    const __nv_bfloat16* Bl = wtl + (size_t)z * FF * FF;
    const int b = m0 >> 11;
    const int node0 = m0 & (NN - 1);

#if HAS_TCGEN05
    uint32_t sbase = smem_u32(smem);
    if (wid == 0) TCGEN05_ALLOC(sbase + OFF_TMEM, 256);
    if (tid == 0) {
        for (int i = 0; i < NSTAGE; i++) MBARRIER_INIT(sbase + OFF_MBAR + i * 8, 1);
    }
    __syncthreads();
    uint32_t tmem;
    asm volatile("ld.shared.b32 %0, [%1];" : "=r"(tmem) : "r"(sbase + OFF_TMEM));

    auto issue_stage = [&](int it) {
        int s = it & (NSTAGE - 1);
        int k0 = it * 32;
        uint32_t sb = sbase + OFF_BUF + s * STAGE_BYTES;
#pragma unroll
        for (int i = 0; i < 2; i++) {          // A 128 rows x 4 chunks (hi,lo)
            int idx = tid + i * 256;
            int row = idx >> 2;
            int kc = (idx & 3) * 8;
            uint32_t doff = SMEM_SWZ64((uint32_t)(row * 64 + kc * 2));
            CP_ASYNC16(sb + doff,        Ah + (size_t)row * FF + k0 + kc);
            CP_ASYNC16(sb + 8192 + doff, Al + (size_t)row * FF + k0 + kc);
        }
#pragma unroll
        for (int i = 0; i < 4; i++) {          // B 256 rows x 4 chunks (hi,lo)
            int idx = tid + i * 256;
            int row = idx >> 2;
            int kc = (idx & 3) * 8;
            uint32_t doff = SMEM_SWZ64((uint32_t)(row * 64 + kc * 2));
            CP_ASYNC16(sb + 16384 + doff, Bh + (size_t)row * FF + k0 + kc);
            CP_ASYNC16(sb + 32768 + doff, Bl + (size_t)row * FF + k0 + kc);
        }
    };

    const int NIT = FF / 32;   // 8
    issue_stage(0); CP_COMMIT();
    issue_stage(1); CP_COMMIT();
    issue_stage(2); CP_COMMIT();

    int ph[NSTAGE] = {0, 0, 0, 0};
    for (int it = 0; it < NIT; it++) {
        int s = it & (NSTAGE - 1);
        CP_WAIT(2);
        __syncthreads();
        if (wid == 0) {
            FENCE_PROXY_ASYNC();
            if (elect_one_pred()) {
                uint32_t sb = sbase + OFF_BUF + s * STAGE_BYTES;
                uint64_t dA[2] = { MAKE_DESC64(sb),         MAKE_DESC64(sb + 8192) };
                uint64_t dB[2] = { MAKE_DESC64(sb + 16384), MAKE_DESC64(sb + 32768) };
#pragma unroll
                for (int p = 0; p < 3; p++) {
                    int ai = (p == 2) ? 1 : 0;
                    int bi2 = (p == 1) ? 1 : 0;
#pragma unroll
                    for (int ks = 0; ks < 2; ks++) {
                        uint32_t en = !(it == 0 && p == 0 && ks == 0);
                        mma_bf16_ss(tmem, dA[ai] + ks * 2, dB[bi2] + ks * 2, MMA_IDESC, en);
                    }
                }
                TCGEN05_COMMIT(sbase + OFF_MBAR + s * 8);
            }
        }
        if (it + 3 < NIT) {
            if (it >= 1) {
                int so = (it - 1) & (NSTAGE - 1);
                MBARRIER_WAIT_PARITY(sbase + OFF_MBAR + so * 8, ph[so]);
                ph[so] ^= 1;
            }
            issue_stage(it + 3);
        }
        CP_COMMIT();
    }
    {
        int sl = (NIT - 1) & (NSTAGE - 1);
        MBARRIER_WAIT_PARITY(sbase + OFF_MBAR + sl * 8, ph[sl]);
    }
    CP_WAIT(0);
    TCGEN05_FENCE_AFTER();
    __syncthreads();

    // ---- epilogue: TMEM -> smem Ct[feat][node] -> coalesced BT hi/lo ------
    float* Ct = (float*)(smem + OFF_BUF);      // [256][128]
    {
        int sp = wid & 3;
        int half = wid >> 2;
        int node = sp * 32 + lid;
#pragma unroll
        for (int c2 = 0; c2 < 4; c2++) {
            uint32_t dr[32];
            TCGEN05_LD_32X32B_X32(dr, tmem + half * 128 + c2 * 32);
            TCGEN05_WAIT_LD();
            int f0 = half * 128 + c2 * 32;
#pragma unroll
            for (int c = 0; c < 32; c++)
                Ct[(f0 + c) * 128 + node] = __uint_as_float(dr[c]);
        }
        TCGEN05_FENCE_BEFORE();
    }
    __syncthreads();
    {
        // warp wid handles feats wid*32..wid*32+31; lane covers 4 nodes
#pragma unroll 4
        for (int j = 0; j < 32; j++) {
            int f = wid * 32 + j;
            float4 vv = *(const float4*)(Ct + f * 128 + lid * 4);
            union { __nv_bfloat16 h[4]; uint2 u; } H, L;
            split1(vv.x, H.h[0], L.h[0]);
            split1(vv.y, H.h[1], L.h[1]);
            split1(vv.z, H.h[2], L.h[2]);
            split1(vv.w, H.h[3], L.h[3]);
            size_t rowbase = ((size_t)b * NFEAT + z * 256 + f) * NN + node0 + lid * 4;
            *(uint2*)(BTh + rowbase) = H.u;
            *(uint2*)(BTl + rowbase) = L.u;
        }
    }
    __syncthreads();
    if (tid == 0) {
        for (int i = 0; i < NSTAGE; i++) MBARRIER_INVAL(sbase + OFF_MBAR + i * 8);
    }
    __syncthreads();
    if (wid == 0) {
        TCGEN05_RELINQUISH();
        TCGEN05_DEALLOC(tmem, 256);
    }
#else
    // correct (slow) fallback — never runs when sm_103a SASS is present
    for (int e = tid; e < 128 * 256; e += 256) {
        int mi = e >> 8, nj = e & 255;
        float acc = 0.f;
        for (int k = 0; k < FF; k++) {
            float av = __bfloat162float(Ah[(size_t)mi * FF + k]) +
                       __bfloat162float(Al[(size_t)mi * FF + k]);
            float bv = __bfloat162float(Bh[(size_t)nj * FF + k]) +
                       __bfloat162float(Bl[(size_t)nj * FF + k]);
            acc += av * bv;
        }
        __nv_bfloat16 hi, lo;
        split1(acc, hi, lo);
        size_t o = ((size_t)b * NFEAT + z * 256 + nj) * NN + node0 + mi;
        BTh[o] = hi;
        BTl[o] = lo;
    }
#endif
}

// ============== kernel 5: attn_mma: out = elu(att @ [Wh|wl]) ================
// M=128, N=256 per CTA; K=2048 in 64 tiles of 32; 4-stage x 48KB pipeline.
__global__ void __launch_bounds__(256, 1)
attn_mma(const __nv_bfloat16* __restrict__ att_hi, const __nv_bfloat16* __restrict__ att_lo,
         const __nv_bfloat16* __restrict__ BTh, const __nv_bfloat16* __restrict__ BTl,
         float* __restrict__ out) {
    extern __shared__ char smem[];
    const int tid = threadIdx.x;
    const int wid = tid >> 5;
    const int lid = tid & 31;
    const int b = blockIdx.z;
    const int m0 = blockIdx.x * 128;
    const int n0g = blockIdx.y * 256;     // 0 -> out1, 256 -> out2
    const __nv_bfloat16* Ah = att_hi + (size_t)b * NN * NN;
    const __nv_bfloat16* Al = att_lo + (size_t)b * NN * NN;
    const __nv_bfloat16* Bh = BTh + (size_t)b * NFEAT * NN + (size_t)n0g * NN;
    const __nv_bfloat16* Bl = BTl + (size_t)b * NFEAT * NN + (size_t)n0g * NN;

#if HAS_TCGEN05
    uint32_t sbase = smem_u32(smem);
    if (wid == 0) TCGEN05_ALLOC(sbase + OFF_TMEM, 256);
    if (tid == 0) {
        for (int i = 0; i < NSTAGE; i++) MBARRIER_INIT(sbase + OFF_MBAR + i * 8, 1);
    }
    __syncthreads();
    uint32_t tmem;
    asm volatile("ld.shared.b32 %0, [%1];" : "=r"(tmem) : "r"(sbase + OFF_TMEM));

    auto issue_stage = [&](int it) {
        int s = it & (NSTAGE - 1);
        int k0 = it * 32;
        uint32_t sb = sbase + OFF_BUF + s * STAGE_BYTES;
#pragma unroll
        for (int i = 0; i < 2; i++) {          // A 128 rows x 4 chunks (hi,lo)
            int idx = tid + i * 256;
            int row = idx >> 2;
            int kc = (idx & 3) * 8;
            uint32_t doff = SMEM_SWZ64((uint32_t)(row * 64 + kc * 2));
            CP_ASYNC16(sb + doff,        Ah + (size_t)(m0 + row) * NN + k0 + kc);
            CP_ASYNC16(sb + 8192 + doff, Al + (size_t)(m0 + row) * NN + k0 + kc);
        }
#pragma unroll
        for (int i = 0; i < 4; i++) {          // B 256 rows x 4 chunks (hi,lo)
            int idx = tid + i * 256;
            int row = idx >> 2;
            int kc = (idx & 3) * 8;
            uint32_t doff = SMEM_SWZ64((uint32_t)(row * 64 + kc * 2));
            CP_ASYNC16(sb + 16384 + doff, Bh + (size_t)row * NN + k0 + kc);
            CP_ASYNC16(sb + 32768 + doff, Bl + (size_t)row * NN + k0 + kc);
        }
    };

    const int NIT = NN / 32;   // 64
    issue_stage(0); CP_COMMIT();
    issue_stage(1); CP_COMMIT();
    issue_stage(2); CP_COMMIT();

    int ph[NSTAGE] = {0, 0, 0, 0};
    for (int it = 0; it < NIT; it++) {
        int s = it & (NSTAGE - 1);
        CP_WAIT(2);
        __syncthreads();
        if (wid == 0) {
            FENCE_PROXY_ASYNC();
            if (elect_one_pred()) {
                uint32_t sb = sbase + OFF_BUF + s * STAGE_BYTES;
                uint64_t dA[2] = { MAKE_DESC64(sb),         MAKE_DESC64(sb + 8192) };
                uint64_t dB[2] = { MAKE_DESC64(sb + 16384), MAKE_DESC64(sb + 32768) };
#pragma unroll
                for (int p = 0; p < 3; p++) {     // hi*hi, hi*lo, lo*hi
                    int ai = (p == 2) ? 1 : 0;
                    int bi2 = (p == 1) ? 1 : 0;
#pragma unroll
                    for (int ks = 0; ks < 2; ks++) {
                        uint32_t en = !(it == 0 && p == 0 && ks == 0);
                        mma_bf16_ss(tmem, dA[ai] + ks * 2, dB[bi2] + ks * 2, MMA_IDESC, en);
                    }
                }
                TCGEN05_COMMIT(sbase + OFF_MBAR + s * 8);
            }
        }
        if (it + 3 < NIT) {
            if (it >= 1) {
                int so = (it - 1) & (NSTAGE - 1);
                MBARRIER_WAIT_PARITY(sbase + OFF_MBAR + so * 8, ph[so]);
                ph[so] ^= 1;
            }
            issue_stage(it + 3);
        }
        CP_COMMIT();
    }
    {
        int sl = (NIT - 1) & (NSTAGE - 1);
        MBARRIER_WAIT_PARITY(sbase + OFF_MBAR + sl * 8, ph[sl]);
    }
    CP_WAIT(0);
    TCGEN05_FENCE_AFTER();
    __syncthreads();

    // ---- epilogue: TMEM -> smem Ct[node][CT_PAD] -> coalesced ELU stores ---
    float* Ct = (float*)(smem + OFF_BUF);      // [128][264]  (16B-aligned rows)
    {
        int sp = wid & 3;
        int half = wid >> 2;
        int node = sp * 32 + lid;
#pragma unroll
        for (int c2 = 0; c2 < 4; c2++) {
            uint32_t dr[32];
            TCGEN05_LD_32X32B_X32(dr, tmem + half * 128 + c2 * 32);
            TCGEN05_WAIT_LD();
            float* crow = Ct + node * CT_PAD + half * 128 + c2 * 32;
#pragma unroll
            for (int c = 0; c < 32; c += 4) {
                float4 vv;
                vv.x = __uint_as_float(dr[c + 0]);
                vv.y = __uint_as_float(dr[c + 1]);
                vv.z = __uint_as_float(dr[c + 2]);
                vv.w = __uint_as_float(dr[c + 3]);
                *(float4*)(crow + c) = vv;     // stride-264 vec4: 2-way conflict max
            }
        }
        TCGEN05_FENCE_BEFORE();
    }
    __syncthreads();
    {
        float* obase = out + (size_t)(n0g >> 8) * BATCH * NN * FF + (size_t)b * NN * FF;
#pragma unroll 2
        for (int r = 0; r < 16; r++) {
            int m = wid * 16 + r;
            const float* crow = Ct + m * CT_PAD;
            float* orow = obase + (size_t)(m0 + m) * FF;
#pragma unroll
            for (int hf = 0; hf < 2; hf++) {
                float4 vv = *(const float4*)(crow + hf * 128 + lid * 4);
                float4 o;
                o.x = elu_f(vv.x); o.y = elu_f(vv.y);
                o.z = elu_f(vv.z); o.w = elu_f(vv.w);
                *(float4*)(orow + hf * 128 + lid * 4) = o;
            }
        }
    }

    __syncthreads();
    if (tid == 0) {
        for (int i = 0; i < NSTAGE; i++) MBARRIER_INVAL(sbase + OFF_MBAR + i * 8);
    }
    __syncthreads();
    if (wid == 0) {
        TCGEN05_RELINQUISH();
        TCGEN05_DEALLOC(tmem, 256);
    }
#else
    // correct (slow) fallback — never runs when sm_103a SASS is present
    for (int e = tid; e < 128 * 256; e += 256) {
        int mi = e >> 8, nj = e & 255;
        float acc = 0.f;
        for (int k = 0; k < NN; k++) {
            float av = __bfloat162float(Ah[(size_t)(m0 + mi) * NN + k]) +
                       __bfloat162float(Al[(size_t)(m0 + mi) * NN + k]);
            float bv = __bfloat162float(Bh[(size_t)nj * NN + k]) +
                       __bfloat162float(Bl[(size_t)nj * NN + k]);
            acc += av * bv;
        }
        out[(size_t)(n0g >> 8) * BATCH * NN * FF + (size_t)b * NN * FF
            + (size_t)(m0 + mi) * FF + nj] = elu_f(acc);
    }
#endif
}

// ---------------------------------------------------------------------------
extern "C" void kernel_launch(void* const* d_in, const int* in_sizes, int n_in,
                              void* d_out, int out_size) {
    const float* h     = (const float*)d_in[0];
    const int*   adj   = (const int*)  d_in[1];
    const float* lrgt1 = (const float*)d_in[2];
    const float* W1    = (const float*)d_in[3];
    const float* W2    = (const float*)d_in[4];
    const float* a     = (const float*)d_in[5];
    float* out = (float*)d_out;

    __nv_bfloat16 *ath, *atl, *bth, *btl, *xh, *xl, *wth, *wtl;
    cudaGetSymbolAddress((void**)&ath, d_att_hi);
    cudaGetSymbolAddress((void**)&atl, d_att_lo);
    cudaGetSymbolAddress((void**)&bth, d_bth);
    cudaGetSymbolAddress((void**)&btl, d_btl);
    cudaGetSymbolAddress((void**)&xh,  d_xh);
    cudaGetSymbolAddress((void**)&xl,  d_xl);
    cudaGetSymbolAddress((void**)&wth, d_wth);
    cudaGetSymbolAddress((void**)&wtl, d_wtl);
    float* s1;  cudaGetSymbolAddress((void**)&s1,  d_s1);
    float* s2;  cudaGetSymbolAddress((void**)&s2,  d_s2);
    float* v;   cudaGetSymbolAddress((void**)&v,   d_v);

    v_kernel<<<1, 256>>>(W1, a, v);
    split_x<<<dim3(BN * FF / 1024, 2), 256>>>(h, lrgt1, xh, xl);
    split_w<<<dim3(FF, 2), 256>>>(W1, W2, wth, wtl);

    cudaFuncSetAttribute(feat_mma, cudaFuncAttributeMaxDynamicSharedMemorySize, MMA_SMEM_BYTES);
    feat_mma<<<dim3(BN / 128, 2), 256, MMA_SMEM_BYTES>>>(xh, xl, wth, wtl, bth, btl);

    scores_kernel<<<BN, 256>>>(h, v, s1, s2);
    softmax_kernel<<<BN, 256>>>(adj, s1, s2, ath, atl);

    cudaFuncSetAttribute(attn_mma, cudaFuncAttributeMaxDynamicSharedMemorySize, MMA_SMEM_BYTES);
    attn_mma<<<dim3(NN / 128, 2, BATCH), 256, MMA_SMEM_BYTES>>>(ath, atl, bth, btl, out);
}